// round 1
// baseline (speedup 1.0000x reference)
#include <cuda_runtime.h>
#include <math.h>

#define SEQ   1024
#define HEAD  64
#define NH    8
#define HDIM  512
#define BN    8            // B*N
#define ROWS  (BN*SEQ)     // 8192
#define EPSV  1e-5f

// ---------------- scratch (device globals; allocation-free rule) ----------------
__device__ __align__(256) float g_sin[SEQ*32];
__device__ __align__(256) float g_cos[SEQ*32];
__device__ __align__(256) float g_scl[SEQ*32];
__device__ __align__(256) float g_Q[NH*BN*SEQ*HEAD];
__device__ __align__(256) float g_K[NH*BN*SEQ*HEAD];
__device__ __align__(256) float g_V[NH*BN*SEQ*HEAD];
__device__ __align__(256) float g_Yc[ROWS*HDIM];
__device__ __align__(256) float g_Z[ROWS*HDIM];

// ---------------- xpos tables in fp64 (matches float64 reference tables) --------
__global__ void tables_kernel() {
    int idx = blockIdx.x * blockDim.x + threadIdx.x;   // 0..32767
    if (idx >= SEQ * 32) return;
    int s = idx >> 5, j = idx & 31;
    double inv_freq = pow(10000.0, -(double)j / 32.0);
    double ang = (double)s * inv_freq;
    g_sin[idx] = (float)sin(ang);
    g_cos[idx] = (float)cos(ang);
    double sv = (2.0 * j + 25.6) / 89.6;               // (2j + 0.4*64)/(1.4*64)
    g_scl[idx] = (float)pow(sv, (double)s / 512.0);
}

// ---------------- QKV projection + rotary epilogue -------------------------------
// grid: (128 row-tiles, 24 = mat*8+g), block 256
__global__ __launch_bounds__(256) void qkv_kernel(
    const float* __restrict__ X,
    const float* __restrict__ Wq,
    const float* __restrict__ Wk,
    const float* __restrict__ Wv)
{
    __shared__ float Xs[64*17];
    __shared__ float Ws[16*68];
    int tid = threadIdx.x;
    int tx = tid & 15, ty = tid >> 4;
    int rowTile = blockIdx.x * 64;
    int mat = blockIdx.y >> 3, g = blockIdx.y & 7;
    const float* W = (mat == 0 ? Wq : (mat == 1 ? Wk : Wv)) + g * (HDIM*HEAD);

    float acc[4][4] = {};
    int lr = tid >> 2, lc = (tid & 3) * 4;     // X tile load mapping
    int wr = tid >> 4, wc = (tid & 15) * 4;    // W tile load mapping

    for (int kk = 0; kk < HDIM; kk += 16) {
        float4 xv = *(const float4*)&X[(size_t)(rowTile + lr)*HDIM + kk + lc];
        Xs[lr*17 + lc + 0] = xv.x; Xs[lr*17 + lc + 1] = xv.y;
        Xs[lr*17 + lc + 2] = xv.z; Xs[lr*17 + lc + 3] = xv.w;
        float4 wv = *(const float4*)&W[(size_t)(kk + wr)*HEAD + wc];
        *(float4*)&Ws[wr*68 + wc] = wv;
        __syncthreads();
        #pragma unroll
        for (int k = 0; k < 16; k++) {
            float4 b = *(const float4*)&Ws[k*68 + tx*4];
            #pragma unroll
            for (int i = 0; i < 4; i++) {
                float a = Xs[(ty*4 + i)*17 + k];
                acc[i][0] = fmaf(a, b.x, acc[i][0]);
                acc[i][1] = fmaf(a, b.y, acc[i][1]);
                acc[i][2] = fmaf(a, b.z, acc[i][2]);
                acc[i][3] = fmaf(a, b.w, acc[i][3]);
            }
        }
        __syncthreads();
    }

    #pragma unroll
    for (int i = 0; i < 4; i++) {
        int row = rowTile + ty*4 + i;
        int bn = row >> 10, s = row & 1023;
        float* dst = (mat == 0 ? g_Q : (mat == 1 ? g_K : g_V))
                     + ((size_t)((g << 3) + bn) * SEQ + s) * HEAD;
        if (mat == 2) {
            #pragma unroll
            for (int j = 0; j < 4; j++) dst[tx*4 + j] = acc[i][j];
        } else {
            #pragma unroll
            for (int p = 0; p < 2; p++) {
                int c = tx*4 + 2*p;
                int j2 = c >> 1;
                float sn = g_sin[s*32 + j2];
                float cs = g_cos[s*32 + j2];
                float sc = g_scl[s*32 + j2];
                float e = acc[i][2*p], o = acc[i][2*p + 1];
                float re = e*cs - o*sn;
                float ro = o*cs + e*sn;
                if (mat == 0) { dst[c] = re * sc;  dst[c+1] = ro * sc; }
                else          { dst[c] = re / sc;  dst[c+1] = ro / sc; }
            }
        }
    }
}

// ---------------- retention (causal decay attention) + group-norm ---------------
// grid: (16 row-tiles, 64 = g*8+bn), block 256, dynamic smem
__global__ __launch_bounds__(256) void ret_kernel(
    const float* __restrict__ gnw, const float* __restrict__ gnb)
{
    extern __shared__ float sh[];
    float* Qs  = sh;                    // [64][65]   Q rows * gamma^s
    float* KsT = sh + 64*65;            // [64][68]   K transposed [d][t] * gamma^-t
    float* Vs  = KsT + 64*68;           // [64][68]   V [t][d]
    float* Ss  = Vs + 64*68;            // [64][65]   scores / Y staging

    int tid = threadIdx.x, tx = tid & 15, ty = tid >> 4;
    int bx = blockIdx.x;
    int gbn = blockIdx.y; int g = gbn >> 3, bn = gbn & 7;
    int s0 = bx * 64;

    double lg = log(1.0/32.0) + (double)g * ((log(1.0/512.0) - log(1.0/32.0)) / 7.0);
    float log2g = (float)log2(1.0 - exp(lg));

    const float* Qg = g_Q + (size_t)gbn * SEQ * HEAD;
    const float* Kg = g_K + (size_t)gbn * SEQ * HEAD;
    const float* Vg = g_V + (size_t)gbn * SEQ * HEAD;

    // load Q tile, row-scaled by gamma^s
    #pragma unroll
    for (int m = 0; m < 4; m++) {
        int lin = tid + m*256;
        int r = lin >> 4, c = (lin & 15) * 4;
        float4 v = *(const float4*)&Qg[(size_t)(s0 + r)*HEAD + c];
        float f = exp2f((float)(s0 + r) * log2g);
        Qs[r*65 + c + 0] = v.x * f; Qs[r*65 + c + 1] = v.y * f;
        Qs[r*65 + c + 2] = v.z * f; Qs[r*65 + c + 3] = v.w * f;
    }

    float accY[4][4] = {};
    for (int jt = 0; jt <= bx; jt++) {
        int t0 = jt * 64;
        __syncthreads();   // Q ready / previous phase-2 done
        // load K (transposed, scaled by gamma^-t) and V
        #pragma unroll
        for (int m = 0; m < 4; m++) {
            int lin = tid + m*256;
            int r = lin >> 4, c = (lin & 15) * 4;
            float4 kv = *(const float4*)&Kg[(size_t)(t0 + r)*HEAD + c];
            float f = exp2f(-(float)(t0 + r) * log2g);
            KsT[(c+0)*68 + r] = kv.x * f; KsT[(c+1)*68 + r] = kv.y * f;
            KsT[(c+2)*68 + r] = kv.z * f; KsT[(c+3)*68 + r] = kv.w * f;
            float4 vv = *(const float4*)&Vg[(size_t)(t0 + r)*HEAD + c];
            *(float4*)&Vs[r*68 + c] = vv;
        }
        __syncthreads();

        // phase 1: S = Q' K'^T (decay folded in)
        float accS[4][4] = {};
        #pragma unroll 16
        for (int k = 0; k < 64; k++) {
            float4 b = *(const float4*)&KsT[k*68 + tx*4];
            #pragma unroll
            for (int i = 0; i < 4; i++) {
                float a = Qs[(ty*4 + i)*65 + k];
                accS[i][0] = fmaf(a, b.x, accS[i][0]);
                accS[i][1] = fmaf(a, b.y, accS[i][1]);
                accS[i][2] = fmaf(a, b.z, accS[i][2]);
                accS[i][3] = fmaf(a, b.w, accS[i][3]);
            }
        }
        bool diag = (jt == bx);
        #pragma unroll
        for (int i = 0; i < 4; i++)
            #pragma unroll
            for (int j = 0; j < 4; j++) {
                float v = accS[i][j];
                if (diag && (tx*4 + j > ty*4 + i)) v = 0.f;  // causal mask (s0==t0)
                Ss[(ty*4 + i)*65 + tx*4 + j] = v;
            }
        __syncthreads();

        // phase 2: Y += S V
        #pragma unroll 16
        for (int k = 0; k < 64; k++) {
            float4 b = *(const float4*)&Vs[k*68 + tx*4];
            #pragma unroll
            for (int i = 0; i < 4; i++) {
                float a = Ss[(ty*4 + i)*65 + k];
                accY[i][0] = fmaf(a, b.x, accY[i][0]);
                accY[i][1] = fmaf(a, b.y, accY[i][1]);
                accY[i][2] = fmaf(a, b.z, accY[i][2]);
                accY[i][3] = fmaf(a, b.w, accY[i][3]);
            }
        }
    }

    // stage Y tile, then group-norm per row (warp per 8 rows)
    __syncthreads();
    #pragma unroll
    for (int i = 0; i < 4; i++)
        #pragma unroll
        for (int j = 0; j < 4; j++)
            Ss[(ty*4 + i)*65 + tx*4 + j] = accY[i][j];
    __syncthreads();

    int wid = tid >> 5, lane = tid & 31;
    float w0 = gnw[g*64 + lane], w1 = gnw[g*64 + lane + 32];
    float b0 = gnb[g*64 + lane], b1 = gnb[g*64 + lane + 32];
    for (int rr = 0; rr < 8; rr++) {
        int row = wid*8 + rr;
        float v0 = Ss[row*65 + lane], v1 = Ss[row*65 + lane + 32];
        float sum = v0 + v1;
        #pragma unroll
        for (int off = 16; off; off >>= 1) sum += __shfl_xor_sync(0xffffffffu, sum, off);
        float mean = sum * 0.015625f;
        float d0 = v0 - mean, d1 = v1 - mean;
        float sq = d0*d0 + d1*d1;
        #pragma unroll
        for (int off = 16; off; off >>= 1) sq += __shfl_xor_sync(0xffffffffu, sq, off);
        float rstd = rsqrtf(sq * 0.015625f + EPSV);
        int s = s0 + row;
        float* dst = g_Yc + ((size_t)(bn*SEQ + s))*HDIM + g*64;
        dst[lane]      = d0 * rstd * w0 + b0;
        dst[lane + 32] = d1 * rstd * w1 + b1;
    }
}

// ---------------- gate GEMM: Z = silu(X @ W_G) * Ycat ----------------------------
// grid: (128 row-tiles, 8 col-tiles), block 256
__global__ __launch_bounds__(256) void gate_kernel(
    const float* __restrict__ X, const float* __restrict__ Wg)
{
    __shared__ float Xs[64*17];
    __shared__ float Ws[16*68];
    int tid = threadIdx.x;
    int tx = tid & 15, ty = tid >> 4;
    int rowTile = blockIdx.x * 64;
    int ct = blockIdx.y * 64;
    float acc[4][4] = {};
    int lr = tid >> 2, lc = (tid & 3) * 4;
    int wr = tid >> 4, wc = (tid & 15) * 4;
    for (int kk = 0; kk < HDIM; kk += 16) {
        float4 xv = *(const float4*)&X[(size_t)(rowTile + lr)*HDIM + kk + lc];
        Xs[lr*17 + lc + 0] = xv.x; Xs[lr*17 + lc + 1] = xv.y;
        Xs[lr*17 + lc + 2] = xv.z; Xs[lr*17 + lc + 3] = xv.w;
        float4 wv = *(const float4*)&Wg[(size_t)(kk + wr)*HDIM + ct + wc];
        *(float4*)&Ws[wr*68 + wc] = wv;
        __syncthreads();
        #pragma unroll
        for (int k = 0; k < 16; k++) {
            float4 b = *(const float4*)&Ws[k*68 + tx*4];
            #pragma unroll
            for (int i = 0; i < 4; i++) {
                float a = Xs[(ty*4 + i)*17 + k];
                acc[i][0] = fmaf(a, b.x, acc[i][0]);
                acc[i][1] = fmaf(a, b.y, acc[i][1]);
                acc[i][2] = fmaf(a, b.z, acc[i][2]);
                acc[i][3] = fmaf(a, b.w, acc[i][3]);
            }
        }
        __syncthreads();
    }
    #pragma unroll
    for (int i = 0; i < 4; i++) {
        int row = rowTile + ty*4 + i;
        #pragma unroll
        for (int j = 0; j < 4; j++) {
            int col = ct + tx*4 + j;
            float gte = acc[i][j];
            float sig = 1.0f / (1.0f + expf(-gte));
            g_Z[(size_t)row*HDIM + col] = gte * sig * g_Yc[(size_t)row*HDIM + col];
        }
    }
}

// ---------------- output GEMM: out = Z @ W_O --------------------------------------
__global__ __launch_bounds__(256) void out_kernel(
    const float* __restrict__ Wo, float* __restrict__ out)
{
    __shared__ float Xs[64*17];
    __shared__ float Ws[16*68];
    int tid = threadIdx.x;
    int tx = tid & 15, ty = tid >> 4;
    int rowTile = blockIdx.x * 64;
    int ct = blockIdx.y * 64;
    float acc[4][4] = {};
    int lr = tid >> 2, lc = (tid & 3) * 4;
    int wr = tid >> 4, wc = (tid & 15) * 4;
    for (int kk = 0; kk < HDIM; kk += 16) {
        float4 xv = *(const float4*)&g_Z[(size_t)(rowTile + lr)*HDIM + kk + lc];
        Xs[lr*17 + lc + 0] = xv.x; Xs[lr*17 + lc + 1] = xv.y;
        Xs[lr*17 + lc + 2] = xv.z; Xs[lr*17 + lc + 3] = xv.w;
        float4 wv = *(const float4*)&Wo[(size_t)(kk + wr)*HDIM + ct + wc];
        *(float4*)&Ws[wr*68 + wc] = wv;
        __syncthreads();
        #pragma unroll
        for (int k = 0; k < 16; k++) {
            float4 b = *(const float4*)&Ws[k*68 + tx*4];
            #pragma unroll
            for (int i = 0; i < 4; i++) {
                float a = Xs[(ty*4 + i)*17 + k];
                acc[i][0] = fmaf(a, b.x, acc[i][0]);
                acc[i][1] = fmaf(a, b.y, acc[i][1]);
                acc[i][2] = fmaf(a, b.z, acc[i][2]);
                acc[i][3] = fmaf(a, b.w, acc[i][3]);
            }
        }
        __syncthreads();
    }
    #pragma unroll
    for (int i = 0; i < 4; i++) {
        int row = rowTile + ty*4 + i;
        #pragma unroll
        for (int j = 0; j < 4; j++)
            out[(size_t)row*HDIM + ct + tx*4 + j] = acc[i][j];
    }
}

// ---------------- launch ----------------------------------------------------------
extern "C" void kernel_launch(void* const* d_in, const int* in_sizes, int n_in,
                              void* d_out, int out_size)
{
    (void)in_sizes; (void)n_in; (void)out_size;
    const float* X   = (const float*)d_in[0];
    const float* Wq  = (const float*)d_in[1];
    const float* Wk  = (const float*)d_in[2];
    const float* Wv  = (const float*)d_in[3];
    const float* Wg  = (const float*)d_in[4];
    const float* Wo  = (const float*)d_in[5];
    const float* gnw = (const float*)d_in[6];
    const float* gnb = (const float*)d_in[7];
    float* out = (float*)d_out;

    const int RET_SMEM = (64*65 + 64*68 + 64*68 + 64*65) * 4;  // 68096 B
    cudaFuncSetAttribute(ret_kernel, cudaFuncAttributeMaxDynamicSharedMemorySize, RET_SMEM);

    tables_kernel<<<128, 256>>>();
    qkv_kernel<<<dim3(128, 24), 256>>>(X, Wq, Wk, Wv);
    ret_kernel<<<dim3(16, 64), 256, RET_SMEM>>>(gnw, gnb);
    gate_kernel<<<dim3(128, 8), 256>>>(X, Wg);
    out_kernel<<<dim3(128, 8), 256>>>(Wo, out);
}

// round 2
// speedup vs baseline: 1.1044x; 1.1044x over previous
#include <cuda_runtime.h>
#include <math.h>

#define SEQ   1024
#define HEAD  64
#define HDIM  512
#define BN    8
#define ROWS  (BN*SEQ)
#define EPSV  1e-5f

// ---------------- scratch (device globals; allocation-free rule) ----------------
__device__ __align__(256) float g_sin[SEQ*32];
__device__ __align__(256) float g_cos[SEQ*32];
__device__ __align__(256) float g_scl[SEQ*32];
__device__ __align__(256) float g_Q[8*BN*SEQ*HEAD];
__device__ __align__(256) float g_K[8*BN*SEQ*HEAD];
__device__ __align__(256) float g_V[8*BN*SEQ*HEAD];
__device__ __align__(256) float g_Yc[ROWS*HDIM];
__device__ __align__(256) float g_Z[ROWS*HDIM];

typedef unsigned long long u64;

// packed f32x2 helpers — ptxas will NOT auto-fuse; must come from PTX
__device__ __forceinline__ u64 bcast2(float x) {
    u64 r; asm("mov.b64 %0, {%1, %1};" : "=l"(r) : "f"(x)); return r;
}
__device__ __forceinline__ void ffma2(u64& d, u64 a, u64 b) {
    asm("fma.rn.f32x2 %0, %1, %2, %0;" : "+l"(d) : "l"(a), "l"(b));
}
__device__ __forceinline__ float2 unpack2(u64 v) {
    float2 r; asm("mov.b64 {%0, %1}, %2;" : "=f"(r.x), "=f"(r.y) : "l"(v)); return r;
}

// ---------------- xpos tables in fp64 ---------------------------------------------
__global__ void tables_kernel() {
    int idx = blockIdx.x * blockDim.x + threadIdx.x;
    if (idx >= SEQ * 32) return;
    int s = idx >> 5, j = idx & 31;
    double inv_freq = pow(10000.0, -(double)j / 32.0);
    double ang = (double)s * inv_freq;
    g_sin[idx] = (float)sin(ang);
    g_cos[idx] = (float)cos(ang);
    double sv = (2.0 * j + 25.6) / 89.6;
    g_scl[idx] = (float)pow(sv, (double)s / 512.0);
}

// ---------------- QKV projection + rotary (128 thr, 128x64 tile, 8x8 micro) ------
__global__ __launch_bounds__(128) void qkv_kernel(
    const float* __restrict__ X,
    const float* __restrict__ Wq,
    const float* __restrict__ Wk,
    const float* __restrict__ Wv)
{
    __shared__ float As[16][132];   // [k][row] transposed
    __shared__ float Bs[16][68];    // [k][col]
    int tid = threadIdx.x;
    int ty = tid >> 3, tx = tid & 7;
    int rowTile = blockIdx.x * 128;
    int mat = blockIdx.y >> 3, g = blockIdx.y & 7;
    const float* W = (mat == 0 ? Wq : (mat == 1 ? Wk : Wv)) + (size_t)g * HDIM * HEAD;

    u64 acc[4][8] = {};

    for (int kk = 0; kk < HDIM; kk += 16) {
        #pragma unroll
        for (int p = 0; p < 4; p++) {
            int lin = p*128 + tid;
            int r = lin >> 2, c4 = (lin & 3) * 4;
            float4 v = *(const float4*)&X[(size_t)(rowTile + r)*HDIM + kk + c4];
            As[c4+0][r] = v.x; As[c4+1][r] = v.y; As[c4+2][r] = v.z; As[c4+3][r] = v.w;
        }
        #pragma unroll
        for (int p = 0; p < 2; p++) {
            int lin = p*128 + tid;
            int wr = lin >> 4, wc = (lin & 15) * 4;
            *(float4*)&Bs[wr][wc] = *(const float4*)&W[(size_t)(kk + wr)*HEAD + wc];
        }
        __syncthreads();
        #pragma unroll
        for (int k = 0; k < 16; k++) {
            ulonglong2 a01 = *(const ulonglong2*)&As[k][ty*8];
            ulonglong2 a23 = *(const ulonglong2*)&As[k][ty*8 + 4];
            u64 a2[4] = {a01.x, a01.y, a23.x, a23.y};
            float4 b0 = *(const float4*)&Bs[k][tx*8];
            float4 b1 = *(const float4*)&Bs[k][tx*8 + 4];
            u64 bb[8] = {bcast2(b0.x), bcast2(b0.y), bcast2(b0.z), bcast2(b0.w),
                         bcast2(b1.x), bcast2(b1.y), bcast2(b1.z), bcast2(b1.w)};
            #pragma unroll
            for (int ip = 0; ip < 4; ip++)
                #pragma unroll
                for (int j = 0; j < 8; j++)
                    ffma2(acc[ip][j], a2[ip], bb[j]);
        }
        __syncthreads();
    }

    float* base = (mat == 0 ? g_Q : (mat == 1 ? g_K : g_V));
    #pragma unroll
    for (int ip = 0; ip < 4; ip++) {
        float rv[2][8];
        #pragma unroll
        for (int j = 0; j < 8; j++) { float2 u = unpack2(acc[ip][j]); rv[0][j] = u.x; rv[1][j] = u.y; }
        #pragma unroll
        for (int h = 0; h < 2; h++) {
            int row = rowTile + ty*8 + ip*2 + h;
            int bn = row >> 10, s = row & 1023;
            float* dst = base + ((size_t)((g << 3) + bn) * SEQ + s) * HEAD + tx*8;
            if (mat == 2) {
                *(float4*)&dst[0] = make_float4(rv[h][0], rv[h][1], rv[h][2], rv[h][3]);
                *(float4*)&dst[4] = make_float4(rv[h][4], rv[h][5], rv[h][6], rv[h][7]);
            } else {
                float ov[8];
                #pragma unroll
                for (int p = 0; p < 4; p++) {
                    int c = tx*8 + 2*p;
                    int j2 = c >> 1;
                    float sn = g_sin[s*32 + j2], cs = g_cos[s*32 + j2], sc = g_scl[s*32 + j2];
                    float e = rv[h][2*p], o = rv[h][2*p + 1];
                    float re = e*cs - o*sn;
                    float ro = o*cs + e*sn;
                    if (mat == 0) { ov[2*p] = re*sc; ov[2*p+1] = ro*sc; }
                    else          { ov[2*p] = re/sc; ov[2*p+1] = ro/sc; }
                }
                *(float4*)&dst[0] = make_float4(ov[0], ov[1], ov[2], ov[3]);
                *(float4*)&dst[4] = make_float4(ov[4], ov[5], ov[6], ov[7]);
            }
        }
    }
}

// ---------------- retention + group-norm (128 thr, 128 q-rows x 64 t per step) ---
__global__ __launch_bounds__(128) void ret_kernel(
    const float* __restrict__ gnw, const float* __restrict__ gnb)
{
    extern __shared__ float sh[];
    float* Qs = sh;               // [64 d][128 s+pad4]  (pitch 132)
    float* Ks = sh + 64*132;      // [64 d][64 t+pad4]   (pitch 68)
    float* Vs = Ks + 64*68;       // [64 t][64 d+pad4]   (pitch 68)
    float* St = Vs + 64*68;       // [64 t][128 s+pad4]  (pitch 132)

    int tid = threadIdx.x;
    int bx = 7 - (int)blockIdx.x;            // heavy tiles first
    int gbn = blockIdx.y, g = gbn >> 3, bn = gbn & 7;
    int s0 = bx * 128;

    double lgd = log(1.0/32.0) + (double)g * ((log(1.0/512.0) - log(1.0/32.0)) / 7.0);
    float log2g = (float)log2(1.0 - exp(lgd));

    const float* Qg = g_Q + (size_t)gbn * SEQ * HEAD;
    const float* Kg = g_K + (size_t)gbn * SEQ * HEAD;
    const float* Vg = g_V + (size_t)gbn * SEQ * HEAD;

    // load Q tile transposed, row-scaled by gamma^s
    #pragma unroll
    for (int p = 0; p < 16; p++) {
        int lin = p*128 + tid;
        int sl = lin >> 4, c4 = (lin & 15) * 4;
        float4 v = *(const float4*)&Qg[(size_t)(s0 + sl)*HEAD + c4];
        float f = exp2f((float)(s0 + sl) * log2g);
        Qs[(c4+0)*132 + sl] = v.x * f;
        Qs[(c4+1)*132 + sl] = v.y * f;
        Qs[(c4+2)*132 + sl] = v.z * f;
        Qs[(c4+3)*132 + sl] = v.w * f;
    }

    int tyT = tid >> 4, txS = tid & 15;   // phase1: 8 t-rows x 8 s-cols per thread
    int ty2 = tid >> 3, tx2 = tid & 7;    // phase2: 8 s-rows x 8 d-cols per thread

    u64 accY[4][8] = {};
    int jtmax = 2*bx + 1;
    for (int jt = 0; jt <= jtmax; jt++) {
        int t0 = jt * 64;
        if (jt) __syncthreads();                 // previous phase2 done
        #pragma unroll
        for (int p = 0; p < 8; p++) {
            int lin = p*128 + tid;
            int tl = lin >> 4, c4 = (lin & 15) * 4;
            float fk = exp2f(-(float)(t0 + tl) * log2g);
            float4 kv = *(const float4*)&Kg[(size_t)(t0 + tl)*HEAD + c4];
            Ks[(c4+0)*68 + tl] = kv.x * fk;
            Ks[(c4+1)*68 + tl] = kv.y * fk;
            Ks[(c4+2)*68 + tl] = kv.z * fk;
            Ks[(c4+3)*68 + tl] = kv.w * fk;
            float4 vv = *(const float4*)&Vg[(size_t)(t0 + tl)*HEAD + c4];
            *(float4*)&Vs[tl*68 + c4] = vv;
        }
        __syncthreads();

        // phase 1: S^T[t][s] = K'·Q'^T  (decay folded into Q/K scales)
        u64 accS[4][8] = {};
        #pragma unroll 8
        for (int k = 0; k < 64; k++) {
            ulonglong2 a01 = *(const ulonglong2*)&Ks[k*68 + tyT*8];
            ulonglong2 a23 = *(const ulonglong2*)&Ks[k*68 + tyT*8 + 4];
            u64 a2[4] = {a01.x, a01.y, a23.x, a23.y};
            float4 q0 = *(const float4*)&Qs[k*132 + txS*8];
            float4 q1 = *(const float4*)&Qs[k*132 + txS*8 + 4];
            u64 bb[8] = {bcast2(q0.x), bcast2(q0.y), bcast2(q0.z), bcast2(q0.w),
                         bcast2(q1.x), bcast2(q1.y), bcast2(q1.z), bcast2(q1.w)};
            #pragma unroll
            for (int ip = 0; ip < 4; ip++)
                #pragma unroll
                for (int j = 0; j < 8; j++)
                    ffma2(accS[ip][j], a2[ip], bb[j]);
        }
        bool diag = (jt >= 2*bx);
        #pragma unroll
        for (int ip = 0; ip < 4; ip++) {
            float rv[2][8];
            #pragma unroll
            for (int j = 0; j < 8; j++) { float2 u = unpack2(accS[ip][j]); rv[0][j] = u.x; rv[1][j] = u.y; }
            #pragma unroll
            for (int h = 0; h < 2; h++) {
                int tl = tyT*8 + ip*2 + h;
                if (diag) {
                    int tg = t0 + tl;
                    #pragma unroll
                    for (int j = 0; j < 8; j++)
                        if (tg > s0 + txS*8 + j) rv[h][j] = 0.f;   // causal mask
                }
                *(float4*)&St[tl*132 + txS*8]     = make_float4(rv[h][0], rv[h][1], rv[h][2], rv[h][3]);
                *(float4*)&St[tl*132 + txS*8 + 4] = make_float4(rv[h][4], rv[h][5], rv[h][6], rv[h][7]);
            }
        }
        __syncthreads();

        // phase 2: Y[s][d] += S^T(t,s)^T · V(t,d)
        #pragma unroll 8
        for (int k = 0; k < 64; k++) {
            ulonglong2 a01 = *(const ulonglong2*)&St[k*132 + ty2*8];
            ulonglong2 a23 = *(const ulonglong2*)&St[k*132 + ty2*8 + 4];
            u64 a2[4] = {a01.x, a01.y, a23.x, a23.y};
            float4 v0 = *(const float4*)&Vs[k*68 + tx2*8];
            float4 v1 = *(const float4*)&Vs[k*68 + tx2*8 + 4];
            u64 bb[8] = {bcast2(v0.x), bcast2(v0.y), bcast2(v0.z), bcast2(v0.w),
                         bcast2(v1.x), bcast2(v1.y), bcast2(v1.z), bcast2(v1.w)};
            #pragma unroll
            for (int ip = 0; ip < 4; ip++)
                #pragma unroll
                for (int j = 0; j < 8; j++)
                    ffma2(accY[ip][j], a2[ip], bb[j]);
        }
    }

    // stage Y tile [128][68] overlaying dead Qs/Ks region, then group-norm
    __syncthreads();
    float* stage = sh;
    #pragma unroll
    for (int ip = 0; ip < 4; ip++) {
        float rv[2][8];
        #pragma unroll
        for (int j = 0; j < 8; j++) { float2 u = unpack2(accY[ip][j]); rv[0][j] = u.x; rv[1][j] = u.y; }
        #pragma unroll
        for (int h = 0; h < 2; h++) {
            int row = ty2*8 + ip*2 + h;
            *(float4*)&stage[row*68 + tx2*8]     = make_float4(rv[h][0], rv[h][1], rv[h][2], rv[h][3]);
            *(float4*)&stage[row*68 + tx2*8 + 4] = make_float4(rv[h][4], rv[h][5], rv[h][6], rv[h][7]);
        }
    }
    __syncthreads();

    int wid = tid >> 5, lane = tid & 31;
    float w0 = gnw[g*64 + lane], w1 = gnw[g*64 + lane + 32];
    float b0 = gnb[g*64 + lane], b1 = gnb[g*64 + lane + 32];
    for (int rr = 0; rr < 32; rr++) {
        int row = wid*32 + rr;
        float v0 = stage[row*68 + lane], v1 = stage[row*68 + lane + 32];
        float sum = v0 + v1;
        #pragma unroll
        for (int off = 16; off; off >>= 1) sum += __shfl_xor_sync(0xffffffffu, sum, off);
        float mean = sum * 0.015625f;
        float d0 = v0 - mean, d1 = v1 - mean;
        float sq = d0*d0 + d1*d1;
        #pragma unroll
        for (int off = 16; off; off >>= 1) sq += __shfl_xor_sync(0xffffffffu, sq, off);
        float rstd = rsqrtf(sq * 0.015625f + EPSV);
        float* dst = g_Yc + ((size_t)(bn*SEQ + s0 + row))*HDIM + g*64;
        dst[lane]      = d0 * rstd * w0 + b0;
        dst[lane + 32] = d1 * rstd * w1 + b1;
    }
}

// ---------------- gate GEMM: Z = silu(X @ W_G) * Ycat (256 thr, 128x128) ---------
__global__ __launch_bounds__(256) void gate_kernel(
    const float* __restrict__ X, const float* __restrict__ Wg)
{
    __shared__ float As[16][132];
    __shared__ float Bs[16][132];
    int tid = threadIdx.x;
    int ty = tid >> 4, tx = tid & 15;
    int rowTile = blockIdx.x * 128, ct = blockIdx.y * 128;
    u64 acc[4][8] = {};

    for (int kk = 0; kk < HDIM; kk += 16) {
        #pragma unroll
        for (int p = 0; p < 2; p++) {
            int lin = p*256 + tid;
            int r = lin >> 2, c4 = (lin & 3) * 4;
            float4 v = *(const float4*)&X[(size_t)(rowTile + r)*HDIM + kk + c4];
            As[c4+0][r] = v.x; As[c4+1][r] = v.y; As[c4+2][r] = v.z; As[c4+3][r] = v.w;
        }
        #pragma unroll
        for (int p = 0; p < 2; p++) {
            int lin = p*256 + tid;
            int wr = lin >> 5, wc = (lin & 31) * 4;
            *(float4*)&Bs[wr][wc] = *(const float4*)&Wg[(size_t)(kk + wr)*HDIM + ct + wc];
        }
        __syncthreads();
        #pragma unroll
        for (int k = 0; k < 16; k++) {
            ulonglong2 a01 = *(const ulonglong2*)&As[k][ty*8];
            ulonglong2 a23 = *(const ulonglong2*)&As[k][ty*8 + 4];
            u64 a2[4] = {a01.x, a01.y, a23.x, a23.y};
            float4 b0 = *(const float4*)&Bs[k][tx*8];
            float4 b1 = *(const float4*)&Bs[k][tx*8 + 4];
            u64 bb[8] = {bcast2(b0.x), bcast2(b0.y), bcast2(b0.z), bcast2(b0.w),
                         bcast2(b1.x), bcast2(b1.y), bcast2(b1.z), bcast2(b1.w)};
            #pragma unroll
            for (int ip = 0; ip < 4; ip++)
                #pragma unroll
                for (int j = 0; j < 8; j++)
                    ffma2(acc[ip][j], a2[ip], bb[j]);
        }
        __syncthreads();
    }

    #pragma unroll
    for (int ip = 0; ip < 4; ip++) {
        float rv[2][8];
        #pragma unroll
        for (int j = 0; j < 8; j++) { float2 u = unpack2(acc[ip][j]); rv[0][j] = u.x; rv[1][j] = u.y; }
        #pragma unroll
        for (int h = 0; h < 2; h++) {
            int row = rowTile + ty*8 + ip*2 + h;
            size_t off = (size_t)row*HDIM + ct + tx*8;
            float4 y0 = *(const float4*)&g_Yc[off];
            float4 y1 = *(const float4*)&g_Yc[off + 4];
            float yv[8] = {y0.x, y0.y, y0.z, y0.w, y1.x, y1.y, y1.z, y1.w};
            float ov[8];
            #pragma unroll
            for (int j = 0; j < 8; j++) {
                float gv = rv[h][j];
                float sig = 1.0f / (1.0f + expf(-gv));
                ov[j] = gv * sig * yv[j];
            }
            *(float4*)&g_Z[off]     = make_float4(ov[0], ov[1], ov[2], ov[3]);
            *(float4*)&g_Z[off + 4] = make_float4(ov[4], ov[5], ov[6], ov[7]);
        }
    }
}

// ---------------- output GEMM: out = Z @ W_O (256 thr, 128x128) -------------------
__global__ __launch_bounds__(256) void out_kernel(
    const float* __restrict__ Wo, float* __restrict__ out)
{
    __shared__ float As[16][132];
    __shared__ float Bs[16][132];
    int tid = threadIdx.x;
    int ty = tid >> 4, tx = tid & 15;
    int rowTile = blockIdx.x * 128, ct = blockIdx.y * 128;
    u64 acc[4][8] = {};

    for (int kk = 0; kk < HDIM; kk += 16) {
        #pragma unroll
        for (int p = 0; p < 2; p++) {
            int lin = p*256 + tid;
            int r = lin >> 2, c4 = (lin & 3) * 4;
            float4 v = *(const float4*)&g_Z[(size_t)(rowTile + r)*HDIM + kk + c4];
            As[c4+0][r] = v.x; As[c4+1][r] = v.y; As[c4+2][r] = v.z; As[c4+3][r] = v.w;
        }
        #pragma unroll
        for (int p = 0; p < 2; p++) {
            int lin = p*256 + tid;
            int wr = lin >> 5, wc = (lin & 31) * 4;
            *(float4*)&Bs[wr][wc] = *(const float4*)&Wo[(size_t)(kk + wr)*HDIM + ct + wc];
        }
        __syncthreads();
        #pragma unroll
        for (int k = 0; k < 16; k++) {
            ulonglong2 a01 = *(const ulonglong2*)&As[k][ty*8];
            ulonglong2 a23 = *(const ulonglong2*)&As[k][ty*8 + 4];
            u64 a2[4] = {a01.x, a01.y, a23.x, a23.y};
            float4 b0 = *(const float4*)&Bs[k][tx*8];
            float4 b1 = *(const float4*)&Bs[k][tx*8 + 4];
            u64 bb[8] = {bcast2(b0.x), bcast2(b0.y), bcast2(b0.z), bcast2(b0.w),
                         bcast2(b1.x), bcast2(b1.y), bcast2(b1.z), bcast2(b1.w)};
            #pragma unroll
            for (int ip = 0; ip < 4; ip++)
                #pragma unroll
                for (int j = 0; j < 8; j++)
                    ffma2(acc[ip][j], a2[ip], bb[j]);
        }
        __syncthreads();
    }

    #pragma unroll
    for (int ip = 0; ip < 4; ip++) {
        float rv[2][8];
        #pragma unroll
        for (int j = 0; j < 8; j++) { float2 u = unpack2(acc[ip][j]); rv[0][j] = u.x; rv[1][j] = u.y; }
        #pragma unroll
        for (int h = 0; h < 2; h++) {
            int row = rowTile + ty*8 + ip*2 + h;
            size_t off = (size_t)row*HDIM + ct + tx*8;
            *(float4*)&out[off]     = make_float4(rv[h][0], rv[h][1], rv[h][2], rv[h][3]);
            *(float4*)&out[off + 4] = make_float4(rv[h][4], rv[h][5], rv[h][6], rv[h][7]);
        }
    }
}

// ---------------- launch ----------------------------------------------------------
extern "C" void kernel_launch(void* const* d_in, const int* in_sizes, int n_in,
                              void* d_out, int out_size)
{
    (void)in_sizes; (void)n_in; (void)out_size;
    const float* X   = (const float*)d_in[0];
    const float* Wq  = (const float*)d_in[1];
    const float* Wk  = (const float*)d_in[2];
    const float* Wv  = (const float*)d_in[3];
    const float* Wg  = (const float*)d_in[4];
    const float* Wo  = (const float*)d_in[5];
    const float* gnw = (const float*)d_in[6];
    const float* gnb = (const float*)d_in[7];
    float* out = (float*)d_out;

    const int RET_SMEM = (64*132 + 64*68 + 64*68 + 64*132) * 4;  // 102400 B
    cudaFuncSetAttribute(ret_kernel, cudaFuncAttributeMaxDynamicSharedMemorySize, RET_SMEM);

    tables_kernel<<<128, 256>>>();
    qkv_kernel<<<dim3(64, 24), 128>>>(X, Wq, Wk, Wv);
    ret_kernel<<<dim3(8, 64), 128, RET_SMEM>>>(gnw, gnb);
    gate_kernel<<<dim3(64, 4), 256>>>(X, Wg);
    out_kernel<<<dim3(64, 4), 256>>>(Wo, out);
}

// round 4
// speedup vs baseline: 1.4857x; 1.3453x over previous
#include <cuda_runtime.h>
#include <cuda_bf16.h>
#include <math.h>
#include <stdint.h>

#define SEQ   1024
#define HEAD  64
#define HDIM  512
#define BN    8
#define ROWS  (BN*SEQ)
#define EPSV  1e-5f

typedef unsigned long long u64;
typedef unsigned int u32;
typedef unsigned short u16;

// ---------------- scratch (device globals; allocation-free rule) ----------------
__device__ __align__(256) float g_sin[SEQ*32];
__device__ __align__(256) float g_cos[SEQ*32];
__device__ __align__(256) float g_scl[SEQ*32];
__device__ __align__(256) float g_Q[8*BN*SEQ*HEAD];
__device__ __align__(256) float g_K[8*BN*SEQ*HEAD];
__device__ __align__(256) float g_V[8*BN*SEQ*HEAD];
__device__ __align__(256) float g_Yc[ROWS*HDIM];
// bf16 hi/lo split operands
__device__ __align__(256) u16 g_Xh[ROWS*HDIM];
__device__ __align__(256) u16 g_Xl[ROWS*HDIM];
__device__ __align__(256) u16 g_Zh[ROWS*HDIM];
__device__ __align__(256) u16 g_Zl[ROWS*HDIM];
__device__ __align__(256) u16 g_WgTh[HDIM*HDIM];
__device__ __align__(256) u16 g_WgTl[HDIM*HDIM];
__device__ __align__(256) u16 g_WoTh[HDIM*HDIM];
__device__ __align__(256) u16 g_WoTl[HDIM*HDIM];
__device__ __align__(256) u16 g_WqkvTh[3*8*HEAD*HDIM];
__device__ __align__(256) u16 g_WqkvTl[3*8*HEAD*HDIM];

// ---------------- helpers ----------------------------------------------------------
__device__ __forceinline__ u32 smem_u32(const void* p) {
    u32 a;
    asm("{ .reg .u64 t; cvta.to.shared.u64 t, %1; cvt.u32.u64 %0, t; }" : "=r"(a) : "l"(p));
    return a;
}
__device__ __forceinline__ void ldsm_x4(u32& r0, u32& r1, u32& r2, u32& r3, u32 addr) {
    asm volatile("ldmatrix.sync.aligned.m8n8.x4.shared.b16 {%0,%1,%2,%3}, [%4];"
        : "=r"(r0), "=r"(r1), "=r"(r2), "=r"(r3) : "r"(addr));
}
__device__ __forceinline__ void ldsm_x2(u32& r0, u32& r1, u32 addr) {
    asm volatile("ldmatrix.sync.aligned.m8n8.x2.shared.b16 {%0,%1}, [%2];"
        : "=r"(r0), "=r"(r1) : "r"(addr));
}
__device__ __forceinline__ void mma_bf16(float* c, const u32* a, u32 b0, u32 b1) {
    asm volatile("mma.sync.aligned.m16n8k16.row.col.f32.bf16.bf16.f32 "
        "{%0,%1,%2,%3}, {%4,%5,%6,%7}, {%8,%9}, {%0,%1,%2,%3};"
        : "+f"(c[0]), "+f"(c[1]), "+f"(c[2]), "+f"(c[3])
        : "r"(a[0]), "r"(a[1]), "r"(a[2]), "r"(a[3]), "r"(b0), "r"(b1));
}
// packed f32x2 helpers for scalar retention kernel
__device__ __forceinline__ u64 bcast2(float x) {
    u64 r; asm("mov.b64 %0, {%1, %1};" : "=l"(r) : "f"(x)); return r;
}
__device__ __forceinline__ void ffma2(u64& d, u64 a, u64 b) {
    asm("fma.rn.f32x2 %0, %1, %2, %0;" : "+l"(d) : "l"(a), "l"(b));
}
__device__ __forceinline__ float2 unpack2(u64 v) {
    float2 r; asm("mov.b64 {%0, %1}, %2;" : "=f"(r.x), "=f"(r.y) : "l"(v)); return r;
}
__device__ __forceinline__ void split_bf(float x, u16& h, u16& l) {
    __nv_bfloat16 hb = __float2bfloat16(x);
    __nv_bfloat16 lb = __float2bfloat16(x - __bfloat162float(hb));
    h = __bfloat16_as_ushort(hb);
    l = __bfloat16_as_ushort(lb);
}

// ---------------- xpos tables in fp64 ---------------------------------------------
__global__ void tables_kernel() {
    int idx = blockIdx.x * blockDim.x + threadIdx.x;
    if (idx >= SEQ * 32) return;
    int s = idx >> 5, j = idx & 31;
    double inv_freq = pow(10000.0, -(double)j / 32.0);
    double ang = (double)s * inv_freq;
    g_sin[idx] = (float)sin(ang);
    g_cos[idx] = (float)cos(ang);
    double sv = (2.0 * j + 25.6) / 89.6;
    g_scl[idx] = (float)pow(sv, (double)s / 512.0);
}

// ---------------- converters -------------------------------------------------------
__global__ __launch_bounds__(256) void convX_kernel(const float* __restrict__ X) {
    int i = blockIdx.x * 256 + threadIdx.x;
    float4 v = ((const float4*)X)[i];
    ushort4 h, l;
    split_bf(v.x, h.x, l.x); split_bf(v.y, h.y, l.y);
    split_bf(v.z, h.z, l.z); split_bf(v.w, h.w, l.w);
    ((ushort4*)g_Xh)[i] = h;
    ((ushort4*)g_Xl)[i] = l;
}
__global__ __launch_bounds__(256) void convW_kernel(const float* __restrict__ W, int which) {
    int i = blockIdx.x * 256 + threadIdx.x;
    int n = i >> 9, k = i & 511;
    float x = W[(size_t)k * HDIM + n];
    u16 h, l; split_bf(x, h, l);
    u16* Th = which ? g_WoTh : g_WgTh;
    u16* Tl = which ? g_WoTl : g_WgTl;
    Th[i] = h; Tl[i] = l;
}
__global__ __launch_bounds__(256) void convWqkv_kernel(
    const float* __restrict__ Wq, const float* __restrict__ Wk, const float* __restrict__ Wv) {
    int i = blockIdx.x * 256 + threadIdx.x;
    int k = i & 511, n = (i >> 9) & 63, g = (i >> 15) & 7, mat = i >> 18;
    const float* W = (mat == 0 ? Wq : (mat == 1 ? Wk : Wv));
    float x = W[(size_t)g * HDIM * HEAD + (size_t)k * HEAD + n];
    u16 h, l; split_bf(x, h, l);
    g_WqkvTh[i] = h; g_WqkvTl[i] = l;
}

// ---------------- mma.sync bf16x3 mainloop -----------------------------------------
// C[128, BROWS] = A[128,512] · B^T (B stored [BROWS,512] K-major). 256 thr, 8 warps 4x2.
// C frag layout per warp: C[(mt*NTI+nt)*4 + ci], mt in 0..1 (m16), nt n-tiles (n8).
#define PITCH 40   // bf16 elems per smem row (80B: conflict-free, 16B-aligned)

template<int BROWS>
__device__ __forceinline__ void mma_mainloop(
    const u16* __restrict__ Ah, const u16* __restrict__ Al,
    const u16* __restrict__ Bh, const u16* __restrict__ Bl,
    char* smem, float* C)
{
    constexpr int NTI   = BROWS / 16;          // n-tiles per warp (warp n = BROWS/2)
    constexpr int ABYT  = 128 * PITCH * 2;
    constexpr int BBYT  = BROWS * PITCH * 2;
    constexpr int STAGE = 2 * ABYT + 2 * BBYT;
    constexpr int AGRAN = 128 * 4;             // uint4 granules per A array
    constexpr int BGRAN = BROWS * 4;
    constexpr int NBUF  = (2 * AGRAN + 2 * BGRAN) / 256;

    int tid = threadIdx.x, lane = tid & 31, wid = tid >> 5;
    int wm = wid & 3, wn = wid >> 2;
    int g4 = lane >> 2, t4 = lane & 3;
    u32 sbase = smem_u32(smem);

    uint4 buf[NBUF];
    // per-thread granule decode (compile-time loop)
    int garr[NBUF], grow[NBUF], gc16[NBUF];
    #pragma unroll
    for (int i = 0; i < NBUF; i++) {
        int g = i * 256 + tid;
        int arr, rem;
        if (g < AGRAN)                { arr = 0; rem = g; }
        else if (g < 2*AGRAN)         { arr = 1; rem = g - AGRAN; }
        else if (g < 2*AGRAN + BGRAN) { arr = 2; rem = g - 2*AGRAN; }
        else                          { arr = 3; rem = g - 2*AGRAN - BGRAN; }
        garr[i] = arr; grow[i] = rem >> 2; gc16[i] = rem & 3;
    }
    const u16* srcs[4] = {Ah, Al, Bh, Bl};
    const int offs[4] = {0, ABYT, 2*ABYT, 2*ABYT + BBYT};

    auto load_regs = [&](int ch) {
        int kk = ch * 32;
        #pragma unroll
        for (int i = 0; i < NBUF; i++)
            buf[i] = *(const uint4*)(srcs[garr[i]] + (size_t)grow[i] * HDIM + kk + gc16[i] * 8);
    };
    auto store_smem = [&](int st) {
        #pragma unroll
        for (int i = 0; i < NBUF; i++)
            *(uint4*)(smem + st*STAGE + offs[garr[i]] + grow[i]*(PITCH*2) + gc16[i]*16) = buf[i];
    };

    // ldmatrix lane-address components
    int aq = lane >> 3, ar = lane & 7;                   // A x4: quad, row-in-8
    int a_row = wm*32 + ar + (aq & 1)*8;                 // + mt*16
    int a_kb  = (aq >> 1) * 8;                           // + ks*16
    int b_row = wn*(BROWS/2) + ar;                       // + nt*8
    int b_kb  = (lane >> 3 & 1) * 8;                     // x2 uses lanes 0..15

    auto compute = [&](int st) {
        u32 sA_h = sbase + st*STAGE;
        u32 sA_l = sA_h + ABYT;
        u32 sB_h = sbase + st*STAGE + 2*ABYT;
        u32 sB_l = sB_h + BBYT;
        #pragma unroll
        for (int ks = 0; ks < 2; ks++) {
            int k0 = ks * 16;
            u32 ah[2][4], al[2][4];
            #pragma unroll
            for (int mt = 0; mt < 2; mt++) {
                u32 ao = (u32)((a_row + mt*16) * (PITCH*2) + (k0 + a_kb) * 2);
                ldsm_x4(ah[mt][0], ah[mt][1], ah[mt][2], ah[mt][3], sA_h + ao);
                ldsm_x4(al[mt][0], al[mt][1], al[mt][2], al[mt][3], sA_l + ao);
            }
            #pragma unroll
            for (int nt = 0; nt < NTI; nt++) {
                u32 bo = (u32)((b_row + nt*8) * (PITCH*2) + (k0 + b_kb) * 2);
                u32 bh0, bh1, bl0, bl1;
                ldsm_x2(bh0, bh1, sB_h + bo);
                ldsm_x2(bl0, bl1, sB_l + bo);
                #pragma unroll
                for (int mt = 0; mt < 2; mt++) {
                    float* c = C + (mt*NTI + nt)*4;
                    mma_bf16(c, ah[mt], bh0, bh1);
                    mma_bf16(c, ah[mt], bl0, bl1);
                    mma_bf16(c, al[mt], bh0, bh1);
                }
            }
        }
    };

    load_regs(0);
    store_smem(0);
    __syncthreads();
    #pragma unroll 1
    for (int ch = 0; ch < 16; ch++) {
        if (ch < 15) load_regs(ch + 1);
        compute(ch & 1);
        if (ch < 15) store_smem((ch + 1) & 1);
        __syncthreads();
    }
}

// ---------------- QKV GEMM + rotary epilogue ---------------------------------------
// grid: (64 row-tiles, 24 = mat*8+g), block 256
__global__ __launch_bounds__(256) void qkv_mma_kernel() {
    extern __shared__ __align__(128) char smem[];
    int rowTile = blockIdx.x * 128;
    int mat = blockIdx.y >> 3, g = blockIdx.y & 7;

    float C[2*4*4] = {};
    mma_mainloop<64>(g_Xh + (size_t)rowTile*HDIM, g_Xl + (size_t)rowTile*HDIM,
                     g_WqkvTh + (size_t)(mat*8 + g)*HEAD*HDIM,
                     g_WqkvTl + (size_t)(mat*8 + g)*HEAD*HDIM, smem, C);

    int tid = threadIdx.x, lane = tid & 31, wid = tid >> 5;
    int wm = wid & 3, wn = wid >> 2, g4 = lane >> 2, t4 = lane & 3;
    float* base = (mat == 0 ? g_Q : (mat == 1 ? g_K : g_V));

    #pragma unroll
    for (int mt = 0; mt < 2; mt++)
        #pragma unroll
        for (int nt = 0; nt < 4; nt++) {
            const float* c = C + (mt*4 + nt)*4;
            int col = wn*32 + nt*8 + t4*2;
            #pragma unroll
            for (int h = 0; h < 2; h++) {
                int row = rowTile + wm*32 + mt*16 + g4 + h*8;
                int bn = row >> 10, s = row & 1023;
                float e = c[h*2], o = c[h*2 + 1];
                float* dst = base + ((size_t)((g << 3) + bn)*SEQ + s)*HEAD + col;
                float2 w;
                if (mat == 2) { w.x = e; w.y = o; }
                else {
                    int j2 = col >> 1;
                    float sn = g_sin[s*32 + j2], cs = g_cos[s*32 + j2], sc = g_scl[s*32 + j2];
                    float re = e*cs - o*sn;
                    float ro = o*cs + e*sn;
                    if (mat == 0) { w.x = re*sc; w.y = ro*sc; }
                    else          { w.x = re/sc; w.y = ro/sc; }
                }
                *(float2*)dst = w;
            }
        }
}

// ---------------- gate GEMM: Z = silu(X@Wg)*Yc -> bf16 hi/lo ------------------------
// grid: (64, 4), block 256
__global__ __launch_bounds__(256) void gate_mma_kernel() {
    extern __shared__ __align__(128) char smem[];
    int rowTile = blockIdx.x * 128, ct = blockIdx.y * 128;

    float C[2*8*4] = {};
    mma_mainloop<128>(g_Xh + (size_t)rowTile*HDIM, g_Xl + (size_t)rowTile*HDIM,
                      g_WgTh + (size_t)ct*HDIM, g_WgTl + (size_t)ct*HDIM, smem, C);

    int tid = threadIdx.x, lane = tid & 31, wid = tid >> 5;
    int wm = wid & 3, wn = wid >> 2, g4 = lane >> 2, t4 = lane & 3;

    #pragma unroll
    for (int mt = 0; mt < 2; mt++)
        #pragma unroll
        for (int nt = 0; nt < 8; nt++) {
            const float* c = C + (mt*8 + nt)*4;
            int col = ct + wn*64 + nt*8 + t4*2;
            #pragma unroll
            for (int h = 0; h < 2; h++) {
                int row = rowTile + wm*32 + mt*16 + g4 + h*8;
                size_t off = (size_t)row*HDIM + col;
                float2 y = *(const float2*)&g_Yc[off];
                float v0 = c[h*2], v1 = c[h*2 + 1];
                float z0 = v0 / (1.0f + expf(-v0)) * y.x;
                float z1 = v1 / (1.0f + expf(-v1)) * y.y;
                u16 h0, l0, h1, l1;
                split_bf(z0, h0, l0);
                split_bf(z1, h1, l1);
                *(u32*)&g_Zh[off] = (u32)h0 | ((u32)h1 << 16);
                *(u32*)&g_Zl[off] = (u32)l0 | ((u32)l1 << 16);
            }
        }
}

// ---------------- output GEMM: out = Z @ Wo ------------------------------------------
__global__ __launch_bounds__(256) void out_mma_kernel(float* __restrict__ out) {
    extern __shared__ __align__(128) char smem[];
    int rowTile = blockIdx.x * 128, ct = blockIdx.y * 128;

    float C[2*8*4] = {};
    mma_mainloop<128>(g_Zh + (size_t)rowTile*HDIM, g_Zl + (size_t)rowTile*HDIM,
                      g_WoTh + (size_t)ct*HDIM, g_WoTl + (size_t)ct*HDIM, smem, C);

    int tid = threadIdx.x, lane = tid & 31, wid = tid >> 5;
    int wm = wid & 3, wn = wid >> 2, g4 = lane >> 2, t4 = lane & 3;

    #pragma unroll
    for (int mt = 0; mt < 2; mt++)
        #pragma unroll
        for (int nt = 0; nt < 8; nt++) {
            const float* c = C + (mt*8 + nt)*4;
            int col = ct + wn*64 + nt*8 + t4*2;
            #pragma unroll
            for (int h = 0; h < 2; h++) {
                int row = rowTile + wm*32 + mt*16 + g4 + h*8;
                *(float2*)&out[(size_t)row*HDIM + col] = make_float2(c[h*2], c[h*2 + 1]);
            }
        }
}

// ---------------- retention + group-norm (scalar FFMA2) -----------------------------
__global__ __launch_bounds__(128) void ret_kernel(
    const float* __restrict__ gnw, const float* __restrict__ gnb)
{
    extern __shared__ float sh[];
    float* Qs = sh;               // [64 d][128 s] pitch 132
    float* Ks = sh + 64*132;      // [64 d][64 t]  pitch 68
    float* Vs = Ks + 64*68;       // [64 t][64 d]  pitch 68
    float* St = Vs + 64*68;       // [64 t][128 s] pitch 132

    int tid = threadIdx.x;
    int bx = 7 - (int)blockIdx.x;
    int gbn = blockIdx.y, g = gbn >> 3, bn = gbn & 7;
    int s0 = bx * 128;

    double lgd = log(1.0/32.0) + (double)g * ((log(1.0/512.0) - log(1.0/32.0)) / 7.0);
    float log2g = (float)log2(1.0 - exp(lgd));

    const float* Qg = g_Q + (size_t)gbn * SEQ * HEAD;
    const float* Kg = g_K + (size_t)gbn * SEQ * HEAD;
    const float* Vg = g_V + (size_t)gbn * SEQ * HEAD;

    #pragma unroll
    for (int p = 0; p < 16; p++) {
        int lin = p*128 + tid;
        int sl = lin >> 4, c4 = (lin & 15) * 4;
        float4 v = *(const float4*)&Qg[(size_t)(s0 + sl)*HEAD + c4];
        float f = exp2f((float)(s0 + sl) * log2g);
        Qs[(c4+0)*132 + sl] = v.x * f;
        Qs[(c4+1)*132 + sl] = v.y * f;
        Qs[(c4+2)*132 + sl] = v.z * f;
        Qs[(c4+3)*132 + sl] = v.w * f;
    }

    int tyT = tid >> 4, txS = tid & 15;
    int ty2 = tid >> 3, tx2 = tid & 7;

    u64 accY[4][8] = {};
    int jtmax = 2*bx + 1;
    for (int jt = 0; jt <= jtmax; jt++) {
        int t0 = jt * 64;
        if (jt) __syncthreads();
        #pragma unroll
        for (int p = 0; p < 8; p++) {
            int lin = p*128 + tid;
            int tl = lin >> 4, c4 = (lin & 15) * 4;
            float fk = exp2f(-(float)(t0 + tl) * log2g);
            float4 kv = *(const float4*)&Kg[(size_t)(t0 + tl)*HEAD + c4];
            Ks[(c4+0)*68 + tl] = kv.x * fk;
            Ks[(c4+1)*68 + tl] = kv.y * fk;
            Ks[(c4+2)*68 + tl] = kv.z * fk;
            Ks[(c4+3)*68 + tl] = kv.w * fk;
            float4 vv = *(const float4*)&Vg[(size_t)(t0 + tl)*HEAD + c4];
            *(float4*)&Vs[tl*68 + c4] = vv;
        }
        __syncthreads();

        u64 accS[4][8] = {};
        #pragma unroll 8
        for (int k = 0; k < 64; k++) {
            ulonglong2 a01 = *(const ulonglong2*)&Ks[k*68 + tyT*8];
            ulonglong2 a23 = *(const ulonglong2*)&Ks[k*68 + tyT*8 + 4];
            u64 a2[4] = {a01.x, a01.y, a23.x, a23.y};
            float4 q0 = *(const float4*)&Qs[k*132 + txS*8];
            float4 q1 = *(const float4*)&Qs[k*132 + txS*8 + 4];
            u64 bb[8] = {bcast2(q0.x), bcast2(q0.y), bcast2(q0.z), bcast2(q0.w),
                         bcast2(q1.x), bcast2(q1.y), bcast2(q1.z), bcast2(q1.w)};
            #pragma unroll
            for (int ip = 0; ip < 4; ip++)
                #pragma unroll
                for (int j = 0; j < 8; j++)
                    ffma2(accS[ip][j], a2[ip], bb[j]);
        }
        bool diag = (jt >= 2*bx);
        #pragma unroll
        for (int ip = 0; ip < 4; ip++) {
            float rv[2][8];
            #pragma unroll
            for (int j = 0; j < 8; j++) { float2 u = unpack2(accS[ip][j]); rv[0][j] = u.x; rv[1][j] = u.y; }
            #pragma unroll
            for (int h = 0; h < 2; h++) {
                int tl = tyT*8 + ip*2 + h;
                if (diag) {
                    int tg = t0 + tl;
                    #pragma unroll
                    for (int j = 0; j < 8; j++)
                        if (tg > s0 + txS*8 + j) rv[h][j] = 0.f;
                }
                *(float4*)&St[tl*132 + txS*8]     = make_float4(rv[h][0], rv[h][1], rv[h][2], rv[h][3]);
                *(float4*)&St[tl*132 + txS*8 + 4] = make_float4(rv[h][4], rv[h][5], rv[h][6], rv[h][7]);
            }
        }
        __syncthreads();

        #pragma unroll 8
        for (int k = 0; k < 64; k++) {
            ulonglong2 a01 = *(const ulonglong2*)&St[k*132 + ty2*8];
            ulonglong2 a23 = *(const ulonglong2*)&St[k*132 + ty2*8 + 4];
            u64 a2[4] = {a01.x, a01.y, a23.x, a23.y};
            float4 v0 = *(const float4*)&Vs[k*68 + tx2*8];
            float4 v1 = *(const float4*)&Vs[k*68 + tx2*8 + 4];
            u64 bb[8] = {bcast2(v0.x), bcast2(v0.y), bcast2(v0.z), bcast2(v0.w),
                         bcast2(v1.x), bcast2(v1.y), bcast2(v1.z), bcast2(v1.w)};
            #pragma unroll
            for (int ip = 0; ip < 4; ip++)
                #pragma unroll
                for (int j = 0; j < 8; j++)
                    ffma2(accY[ip][j], a2[ip], bb[j]);
        }
    }

    __syncthreads();
    float* stage = sh;
    #pragma unroll
    for (int ip = 0; ip < 4; ip++) {
        float rv[2][8];
        #pragma unroll
        for (int j = 0; j < 8; j++) { float2 u = unpack2(accY[ip][j]); rv[0][j] = u.x; rv[1][j] = u.y; }
        #pragma unroll
        for (int h = 0; h < 2; h++) {
            int row = ty2*8 + ip*2 + h;
            *(float4*)&stage[row*68 + tx2*8]     = make_float4(rv[h][0], rv[h][1], rv[h][2], rv[h][3]);
            *(float4*)&stage[row*68 + tx2*8 + 4] = make_float4(rv[h][4], rv[h][5], rv[h][6], rv[h][7]);
        }
    }
    __syncthreads();

    int wid = tid >> 5, lane = tid & 31;
    float w0 = gnw[g*64 + lane], w1 = gnw[g*64 + lane + 32];
    float b0 = gnb[g*64 + lane], b1 = gnb[g*64 + lane + 32];
    for (int rr = 0; rr < 32; rr++) {
        int row = wid*32 + rr;
        float v0 = stage[row*68 + lane], v1 = stage[row*68 + lane + 32];
        float sum = v0 + v1;
        #pragma unroll
        for (int off = 16; off; off >>= 1) sum += __shfl_xor_sync(0xffffffffu, sum, off);
        float mean = sum * 0.015625f;
        float d0 = v0 - mean, d1 = v1 - mean;
        float sq = d0*d0 + d1*d1;
        #pragma unroll
        for (int off = 16; off; off >>= 1) sq += __shfl_xor_sync(0xffffffffu, sq, off);
        float rstd = rsqrtf(sq * 0.015625f + EPSV);
        float* dst = g_Yc + ((size_t)(bn*SEQ + s0 + row))*HDIM + g*64;
        dst[lane]      = d0 * rstd * w0 + b0;
        dst[lane + 32] = d1 * rstd * w1 + b1;
    }
}

// ---------------- launch -------------------------------------------------------------
extern "C" void kernel_launch(void* const* d_in, const int* in_sizes, int n_in,
                              void* d_out, int out_size)
{
    (void)in_sizes; (void)n_in; (void)out_size;
    const float* X   = (const float*)d_in[0];
    const float* Wq  = (const float*)d_in[1];
    const float* Wk  = (const float*)d_in[2];
    const float* Wv  = (const float*)d_in[3];
    const float* Wg  = (const float*)d_in[4];
    const float* Wo  = (const float*)d_in[5];
    const float* gnw = (const float*)d_in[6];
    const float* gnb = (const float*)d_in[7];
    float* out = (float*)d_out;

    const int RET_SMEM = (64*132 + 64*68 + 64*68 + 64*132) * 4;            // 102400
    const int SMEM_128 = 2 * (2*128*PITCH*2 + 2*128*PITCH*2);              // 81920
    const int SMEM_64  = 2 * (2*128*PITCH*2 + 2*64*PITCH*2);               // 61440
    cudaFuncSetAttribute(ret_kernel, cudaFuncAttributeMaxDynamicSharedMemorySize, RET_SMEM);
    cudaFuncSetAttribute(qkv_mma_kernel, cudaFuncAttributeMaxDynamicSharedMemorySize, SMEM_64);
    cudaFuncSetAttribute(gate_mma_kernel, cudaFuncAttributeMaxDynamicSharedMemorySize, SMEM_128);
    cudaFuncSetAttribute(out_mma_kernel, cudaFuncAttributeMaxDynamicSharedMemorySize, SMEM_128);

    tables_kernel<<<128, 256>>>();
    convX_kernel<<<ROWS*HDIM/4/256, 256>>>(X);
    convW_kernel<<<HDIM*HDIM/256, 256>>>(Wg, 0);
    convW_kernel<<<HDIM*HDIM/256, 256>>>(Wo, 1);
    convWqkv_kernel<<<3*8*HEAD*HDIM/256, 256>>>(Wq, Wk, Wv);
    qkv_mma_kernel<<<dim3(64, 24), 256, SMEM_64>>>();
    ret_kernel<<<dim3(8, 64), 128, RET_SMEM>>>(gnw, gnb);
    gate_mma_kernel<<<dim3(64, 4), 256, SMEM_128>>>();
    out_mma_kernel<<<dim3(64, 4), 256, SMEM_128>>>(out);
}

// round 5
// speedup vs baseline: 1.8767x; 1.2632x over previous
#include <cuda_runtime.h>
#include <cuda_bf16.h>
#include <math.h>
#include <stdint.h>

#define SEQ   1024
#define HEAD  64
#define HDIM  512
#define BN    8
#define ROWS  (BN*SEQ)
#define EPSV  1e-5f

typedef unsigned long long u64;
typedef unsigned int u32;
typedef unsigned short u16;

// ---------------- scratch (device globals; allocation-free rule) ----------------
__device__ __align__(256) float g_sin[SEQ*32];
__device__ __align__(256) float g_cos[SEQ*32];
__device__ __align__(256) float g_scl[SEQ*32];
__device__ __align__(256) float g_Q[8*BN*SEQ*HEAD];
__device__ __align__(256) float g_K[8*BN*SEQ*HEAD];
__device__ __align__(256) float g_V[8*BN*SEQ*HEAD];
__device__ __align__(256) float g_Yc[ROWS*HDIM];
__device__ __align__(256) u16 g_Xh[ROWS*HDIM];
__device__ __align__(256) u16 g_Xl[ROWS*HDIM];
__device__ __align__(256) u16 g_Zh[ROWS*HDIM];
__device__ __align__(256) u16 g_Zl[ROWS*HDIM];
__device__ __align__(256) u16 g_WgTh[HDIM*HDIM];
__device__ __align__(256) u16 g_WgTl[HDIM*HDIM];
__device__ __align__(256) u16 g_WoTh[HDIM*HDIM];
__device__ __align__(256) u16 g_WoTl[HDIM*HDIM];
__device__ __align__(256) u16 g_WqkvTh[3*8*HEAD*HDIM];
__device__ __align__(256) u16 g_WqkvTl[3*8*HEAD*HDIM];

// ---------------- helpers ----------------------------------------------------------
__device__ __forceinline__ u32 smem_u32(const void* p) {
    u32 a;
    asm("{ .reg .u64 t; cvta.to.shared.u64 t, %1; cvt.u32.u64 %0, t; }" : "=r"(a) : "l"(p));
    return a;
}
__device__ __forceinline__ void ldsm_x4(u32& r0, u32& r1, u32& r2, u32& r3, u32 addr) {
    asm volatile("ldmatrix.sync.aligned.m8n8.x4.shared.b16 {%0,%1,%2,%3}, [%4];"
        : "=r"(r0), "=r"(r1), "=r"(r2), "=r"(r3) : "r"(addr));
}
__device__ __forceinline__ void ldsm_x2(u32& r0, u32& r1, u32 addr) {
    asm volatile("ldmatrix.sync.aligned.m8n8.x2.shared.b16 {%0,%1}, [%2];"
        : "=r"(r0), "=r"(r1) : "r"(addr));
}
__device__ __forceinline__ void mma_bf16(float* c, const u32* a, u32 b0, u32 b1) {
    asm volatile("mma.sync.aligned.m16n8k16.row.col.f32.bf16.bf16.f32 "
        "{%0,%1,%2,%3}, {%4,%5,%6,%7}, {%8,%9}, {%0,%1,%2,%3};"
        : "+f"(c[0]), "+f"(c[1]), "+f"(c[2]), "+f"(c[3])
        : "r"(a[0]), "r"(a[1]), "r"(a[2]), "r"(a[3]), "r"(b0), "r"(b1));
}
__device__ __forceinline__ void split_bf(float x, u16& h, u16& l) {
    __nv_bfloat16 hb = __float2bfloat16(x);
    __nv_bfloat16 lb = __float2bfloat16(x - __bfloat162float(hb));
    h = __bfloat16_as_ushort(hb);
    l = __bfloat16_as_ushort(lb);
}

// ---------------- xpos tables in fp64 ---------------------------------------------
__global__ void tables_kernel() {
    int idx = blockIdx.x * blockDim.x + threadIdx.x;
    if (idx >= SEQ * 32) return;
    int s = idx >> 5, j = idx & 31;
    double inv_freq = pow(10000.0, -(double)j / 32.0);
    double ang = (double)s * inv_freq;
    g_sin[idx] = (float)sin(ang);
    g_cos[idx] = (float)cos(ang);
    double sv = (2.0 * j + 25.6) / 89.6;
    g_scl[idx] = (float)pow(sv, (double)s / 512.0);
}

// ---------------- converters -------------------------------------------------------
__global__ __launch_bounds__(256) void convX_kernel(const float* __restrict__ X) {
    int i = blockIdx.x * 256 + threadIdx.x;
    float4 v = ((const float4*)X)[i];
    ushort4 h, l;
    split_bf(v.x, h.x, l.x); split_bf(v.y, h.y, l.y);
    split_bf(v.z, h.z, l.z); split_bf(v.w, h.w, l.w);
    ((ushort4*)g_Xh)[i] = h;
    ((ushort4*)g_Xl)[i] = l;
}
__global__ __launch_bounds__(256) void convW_kernel(const float* __restrict__ W, int which) {
    int i = blockIdx.x * 256 + threadIdx.x;
    int n = i >> 9, k = i & 511;
    float x = W[(size_t)k * HDIM + n];
    u16 h, l; split_bf(x, h, l);
    u16* Th = which ? g_WoTh : g_WgTh;
    u16* Tl = which ? g_WoTl : g_WgTl;
    Th[i] = h; Tl[i] = l;
}
__global__ __launch_bounds__(256) void convWqkv_kernel(
    const float* __restrict__ Wq, const float* __restrict__ Wk, const float* __restrict__ Wv) {
    int i = blockIdx.x * 256 + threadIdx.x;
    int k = i & 511, n = (i >> 9) & 63, g = (i >> 15) & 7, mat = i >> 18;
    const float* W = (mat == 0 ? Wq : (mat == 1 ? Wk : Wv));
    float x = W[(size_t)g * HDIM * HEAD + (size_t)k * HEAD + n];
    u16 h, l; split_bf(x, h, l);
    g_WqkvTh[i] = h; g_WqkvTl[i] = l;
}

// ---------------- mma.sync bf16x3 mainloop (GEMM stages) ---------------------------
#define PITCH 40

template<int BROWS>
__device__ __forceinline__ void mma_mainloop(
    const u16* __restrict__ Ah, const u16* __restrict__ Al,
    const u16* __restrict__ Bh, const u16* __restrict__ Bl,
    char* smem, float* C)
{
    constexpr int NTI   = BROWS / 16;
    constexpr int ABYT  = 128 * PITCH * 2;
    constexpr int BBYT  = BROWS * PITCH * 2;
    constexpr int STAGE = 2 * ABYT + 2 * BBYT;
    constexpr int AGRAN = 128 * 4;
    constexpr int BGRAN = BROWS * 4;
    constexpr int NBUF  = (2 * AGRAN + 2 * BGRAN) / 256;

    int tid = threadIdx.x, lane = tid & 31, wid = tid >> 5;
    int wm = wid & 3, wn = wid >> 2;
    u32 sbase = smem_u32(smem);

    uint4 buf[NBUF];
    int garr[NBUF], grow[NBUF], gc16[NBUF];
    #pragma unroll
    for (int i = 0; i < NBUF; i++) {
        int g = i * 256 + tid;
        int arr, rem;
        if (g < AGRAN)                { arr = 0; rem = g; }
        else if (g < 2*AGRAN)         { arr = 1; rem = g - AGRAN; }
        else if (g < 2*AGRAN + BGRAN) { arr = 2; rem = g - 2*AGRAN; }
        else                          { arr = 3; rem = g - 2*AGRAN - BGRAN; }
        garr[i] = arr; grow[i] = rem >> 2; gc16[i] = rem & 3;
    }
    const u16* srcs[4] = {Ah, Al, Bh, Bl};
    const int offs[4] = {0, ABYT, 2*ABYT, 2*ABYT + BBYT};

    auto load_regs = [&](int ch) {
        int kk = ch * 32;
        #pragma unroll
        for (int i = 0; i < NBUF; i++)
            buf[i] = *(const uint4*)(srcs[garr[i]] + (size_t)grow[i] * HDIM + kk + gc16[i] * 8);
    };
    auto store_smem = [&](int st) {
        #pragma unroll
        for (int i = 0; i < NBUF; i++)
            *(uint4*)(smem + st*STAGE + offs[garr[i]] + grow[i]*(PITCH*2) + gc16[i]*16) = buf[i];
    };

    int aq = lane >> 3, ar = lane & 7;
    int a_row = wm*32 + ar + (aq & 1)*8;
    int a_kb  = (aq >> 1) * 8;
    int b_row = wn*(BROWS/2) + ar;
    int b_kb  = (lane >> 3 & 1) * 8;

    auto compute = [&](int st) {
        u32 sA_h = sbase + st*STAGE;
        u32 sA_l = sA_h + ABYT;
        u32 sB_h = sbase + st*STAGE + 2*ABYT;
        u32 sB_l = sB_h + BBYT;
        #pragma unroll
        for (int ks = 0; ks < 2; ks++) {
            int k0 = ks * 16;
            u32 ah[2][4], al[2][4];
            #pragma unroll
            for (int mt = 0; mt < 2; mt++) {
                u32 ao = (u32)((a_row + mt*16) * (PITCH*2) + (k0 + a_kb) * 2);
                ldsm_x4(ah[mt][0], ah[mt][1], ah[mt][2], ah[mt][3], sA_h + ao);
                ldsm_x4(al[mt][0], al[mt][1], al[mt][2], al[mt][3], sA_l + ao);
            }
            #pragma unroll
            for (int nt = 0; nt < NTI; nt++) {
                u32 bo = (u32)((b_row + nt*8) * (PITCH*2) + (k0 + b_kb) * 2);
                u32 bh0, bh1, bl0, bl1;
                ldsm_x2(bh0, bh1, sB_h + bo);
                ldsm_x2(bl0, bl1, sB_l + bo);
                #pragma unroll
                for (int mt = 0; mt < 2; mt++) {
                    float* c = C + (mt*NTI + nt)*4;
                    mma_bf16(c, ah[mt], bh0, bh1);
                    mma_bf16(c, ah[mt], bl0, bl1);
                    mma_bf16(c, al[mt], bh0, bh1);
                }
            }
        }
    };

    load_regs(0);
    store_smem(0);
    __syncthreads();
    #pragma unroll 1
    for (int ch = 0; ch < 16; ch++) {
        if (ch < 15) load_regs(ch + 1);
        compute(ch & 1);
        if (ch < 15) store_smem((ch + 1) & 1);
        __syncthreads();
    }
}

// ---------------- QKV GEMM + rotary epilogue ---------------------------------------
__global__ __launch_bounds__(256) void qkv_mma_kernel() {
    extern __shared__ __align__(128) char smem[];
    int rowTile = blockIdx.x * 128;
    int mat = blockIdx.y >> 3, g = blockIdx.y & 7;

    float C[2*4*4] = {};
    mma_mainloop<64>(g_Xh + (size_t)rowTile*HDIM, g_Xl + (size_t)rowTile*HDIM,
                     g_WqkvTh + (size_t)(mat*8 + g)*HEAD*HDIM,
                     g_WqkvTl + (size_t)(mat*8 + g)*HEAD*HDIM, smem, C);

    int tid = threadIdx.x, lane = tid & 31, wid = tid >> 5;
    int wm = wid & 3, wn = wid >> 2, g4 = lane >> 2, t4 = lane & 3;
    float* base = (mat == 0 ? g_Q : (mat == 1 ? g_K : g_V));

    #pragma unroll
    for (int mt = 0; mt < 2; mt++)
        #pragma unroll
        for (int nt = 0; nt < 4; nt++) {
            const float* c = C + (mt*4 + nt)*4;
            int col = wn*32 + nt*8 + t4*2;
            #pragma unroll
            for (int h = 0; h < 2; h++) {
                int row = rowTile + wm*32 + mt*16 + g4 + h*8;
                int bn = row >> 10, s = row & 1023;
                float e = c[h*2], o = c[h*2 + 1];
                float* dst = base + ((size_t)((g << 3) + bn)*SEQ + s)*HEAD + col;
                float2 w;
                if (mat == 2) { w.x = e; w.y = o; }
                else {
                    int j2 = col >> 1;
                    float sn = g_sin[s*32 + j2], cs = g_cos[s*32 + j2], sc = g_scl[s*32 + j2];
                    float re = e*cs - o*sn;
                    float ro = o*cs + e*sn;
                    if (mat == 0) { w.x = re*sc; w.y = ro*sc; }
                    else          { w.x = re/sc; w.y = ro/sc; }
                }
                *(float2*)dst = w;
            }
        }
}

// ---------------- gate GEMM: Z = silu(X@Wg)*Yc -> bf16 hi/lo ------------------------
__global__ __launch_bounds__(256) void gate_mma_kernel() {
    extern __shared__ __align__(128) char smem[];
    int rowTile = blockIdx.x * 128, ct = blockIdx.y * 128;

    float C[2*8*4] = {};
    mma_mainloop<128>(g_Xh + (size_t)rowTile*HDIM, g_Xl + (size_t)rowTile*HDIM,
                      g_WgTh + (size_t)ct*HDIM, g_WgTl + (size_t)ct*HDIM, smem, C);

    int tid = threadIdx.x, lane = tid & 31, wid = tid >> 5;
    int wm = wid & 3, wn = wid >> 2, g4 = lane >> 2, t4 = lane & 3;

    #pragma unroll
    for (int mt = 0; mt < 2; mt++)
        #pragma unroll
        for (int nt = 0; nt < 8; nt++) {
            const float* c = C + (mt*8 + nt)*4;
            int col = ct + wn*64 + nt*8 + t4*2;
            #pragma unroll
            for (int h = 0; h < 2; h++) {
                int row = rowTile + wm*32 + mt*16 + g4 + h*8;
                size_t off = (size_t)row*HDIM + col;
                float2 y = *(const float2*)&g_Yc[off];
                float v0 = c[h*2], v1 = c[h*2 + 1];
                float z0 = v0 / (1.0f + expf(-v0)) * y.x;
                float z1 = v1 / (1.0f + expf(-v1)) * y.y;
                u16 h0, l0, h1, l1;
                split_bf(z0, h0, l0);
                split_bf(z1, h1, l1);
                *(u32*)&g_Zh[off] = (u32)h0 | ((u32)h1 << 16);
                *(u32*)&g_Zl[off] = (u32)l0 | ((u32)l1 << 16);
            }
        }
}

// ---------------- output GEMM: out = Z @ Wo ------------------------------------------
__global__ __launch_bounds__(256) void out_mma_kernel(float* __restrict__ out) {
    extern __shared__ __align__(128) char smem[];
    int rowTile = blockIdx.x * 128, ct = blockIdx.y * 128;

    float C[2*8*4] = {};
    mma_mainloop<128>(g_Zh + (size_t)rowTile*HDIM, g_Zl + (size_t)rowTile*HDIM,
                      g_WoTh + (size_t)ct*HDIM, g_WoTl + (size_t)ct*HDIM, smem, C);

    int tid = threadIdx.x, lane = tid & 31, wid = tid >> 5;
    int wm = wid & 3, wn = wid >> 2, g4 = lane >> 2, t4 = lane & 3;

    #pragma unroll
    for (int mt = 0; mt < 2; mt++)
        #pragma unroll
        for (int nt = 0; nt < 8; nt++) {
            const float* c = C + (mt*8 + nt)*4;
            int col = ct + wn*64 + nt*8 + t4*2;
            #pragma unroll
            for (int h = 0; h < 2; h++) {
                int row = rowTile + wm*32 + mt*16 + g4 + h*8;
                *(float2*)&out[(size_t)row*HDIM + col] = make_float2(c[h*2], c[h*2 + 1]);
            }
        }
}

// ---------------- retention via tensor cores + group-norm ---------------------------
// grid: (8, 64 = gbn), block 256 (8 warps, 4x2).
// smem (bytes): Qh 0, Ql 18432, Kh 36864, Kl 46080, Vh 55296, Vl 64512, Sh 73728, Sl 92160
// Q/S: 128 rows x 144B (pitch 72 bf16).  K/V: 64 rows x 144B.
#define RP 72
__global__ __launch_bounds__(256) void ret_mma_kernel(
    const float* __restrict__ gnw, const float* __restrict__ gnb)
{
    extern __shared__ __align__(128) char smem[];
    const int QH = 0, QL = 18432, KH = 36864, KL = 46080,
              VH = 55296, VL = 64512, SH = 73728, SL = 92160;
    u32 sbase = smem_u32(smem);

    int tid = threadIdx.x, lane = tid & 31, wid = tid >> 5;
    int wm = wid & 3, wn = wid >> 2;
    int g4 = lane >> 2, t4 = lane & 3;
    int bx = 7 - (int)blockIdx.x;            // heavy tiles first
    int gbn = blockIdx.y, g = gbn >> 3, bn = gbn & 7;
    int s0 = bx * 128;

    double lgd = log(1.0/32.0) + (double)g * ((log(1.0/512.0) - log(1.0/32.0)) / 7.0);
    float log2g = (float)log2(1.0 - exp(lgd));

    const float* Qg = g_Q + (size_t)gbn * SEQ * HEAD;
    const float* Kg = g_K + (size_t)gbn * SEQ * HEAD;
    const float* Vg = g_V + (size_t)gbn * SEQ * HEAD;

    // load Q tile (128x64), scale by gamma^s, split bf16 hi/lo
    #pragma unroll
    for (int p = 0; p < 8; p++) {
        int lin = p*256 + tid;
        int r = lin >> 4, c4 = (lin & 15) * 4;
        float4 v = *(const float4*)&Qg[(size_t)(s0 + r)*HEAD + c4];
        float f = exp2f((float)(s0 + r) * log2g);
        u16 h0,l0,h1,l1,h2,l2,h3,l3;
        split_bf(v.x*f, h0, l0); split_bf(v.y*f, h1, l1);
        split_bf(v.z*f, h2, l2); split_bf(v.w*f, h3, l3);
        u32 off = (u32)r*144 + (u32)c4*2;
        *(u32*)(smem + QH + off)     = (u32)h0 | ((u32)h1 << 16);
        *(u32*)(smem + QH + off + 4) = (u32)h2 | ((u32)h3 << 16);
        *(u32*)(smem + QL + off)     = (u32)l0 | ((u32)l1 << 16);
        *(u32*)(smem + QL + off + 4) = (u32)l2 | ((u32)l3 << 16);
    }

    // ldmatrix addressing
    int aq = lane >> 3, ar = lane & 7;
    int a_row = wm*32 + ar + (aq & 1)*8;
    int a_kb  = (aq >> 1) * 8;
    int b_kb  = (lane >> 3 & 1) * 8;

    float accY[2*4*4] = {};
    int jtmax = 2*bx + 1;
    for (int jt = 0; jt <= jtmax; jt++) {
        int t0 = jt * 64;
        __syncthreads();        // prior phase2 done (and Q stores on first iter)

        // load K (scaled gamma^-t) and V (transposed [d][t]), split bf16
        #pragma unroll
        for (int p = 0; p < 4; p++) {
            int lin = p*256 + tid;
            int r = lin >> 4, c4 = (lin & 15) * 4;
            float fk = exp2f(-(float)(t0 + r) * log2g);
            float4 kv = *(const float4*)&Kg[(size_t)(t0 + r)*HEAD + c4];
            u16 h0,l0,h1,l1,h2,l2,h3,l3;
            split_bf(kv.x*fk, h0, l0); split_bf(kv.y*fk, h1, l1);
            split_bf(kv.z*fk, h2, l2); split_bf(kv.w*fk, h3, l3);
            u32 off = (u32)r*144 + (u32)c4*2;
            *(u32*)(smem + KH + off)     = (u32)h0 | ((u32)h1 << 16);
            *(u32*)(smem + KH + off + 4) = (u32)h2 | ((u32)h3 << 16);
            *(u32*)(smem + KL + off)     = (u32)l0 | ((u32)l1 << 16);
            *(u32*)(smem + KL + off + 4) = (u32)l2 | ((u32)l3 << 16);

            float4 vv = *(const float4*)&Vg[(size_t)(t0 + r)*HEAD + c4];
            float vf[4] = {vv.x, vv.y, vv.z, vv.w};
            #pragma unroll
            for (int q = 0; q < 4; q++) {
                u16 vh, vl; split_bf(vf[q], vh, vl);
                u32 voff = (u32)(c4 + q)*144 + (u32)r*2;
                *(u16*)(smem + VH + voff) = vh;
                *(u16*)(smem + VL + voff) = vl;
            }
        }
        __syncthreads();

        // phase 1: S = Q'·K'^T  (M=128, N=64 t, K=64 d)
        float accS[2*4*4] = {};
        #pragma unroll
        for (int ks = 0; ks < 4; ks++) {
            int k0 = ks * 16;
            u32 ah[2][4], al[2][4];
            #pragma unroll
            for (int mt = 0; mt < 2; mt++) {
                u32 ao = (u32)((a_row + mt*16)*144 + (k0 + a_kb)*2);
                ldsm_x4(ah[mt][0], ah[mt][1], ah[mt][2], ah[mt][3], sbase + QH + ao);
                ldsm_x4(al[mt][0], al[mt][1], al[mt][2], al[mt][3], sbase + QL + ao);
            }
            #pragma unroll
            for (int nt = 0; nt < 4; nt++) {
                u32 bo = (u32)((wn*32 + nt*8 + ar)*144 + (k0 + b_kb)*2);
                u32 bh0, bh1, bl0, bl1;
                ldsm_x2(bh0, bh1, sbase + KH + bo);
                ldsm_x2(bl0, bl1, sbase + KL + bo);
                #pragma unroll
                for (int mt = 0; mt < 2; mt++) {
                    float* c = accS + (mt*4 + nt)*4;
                    mma_bf16(c, ah[mt], bh0, bh1);
                    mma_bf16(c, ah[mt], bl0, bl1);
                    mma_bf16(c, al[mt], bh0, bh1);
                }
            }
        }

        // mask (diag tiles) + split to bf16 hi/lo into Sh/Sl
        bool diag = (jt >= 2*bx);
        #pragma unroll
        for (int mt = 0; mt < 2; mt++)
            #pragma unroll
            for (int nt = 0; nt < 4; nt++) {
                const float* c = accS + (mt*4 + nt)*4;
                int tcol = wn*32 + nt*8 + t4*2;
                #pragma unroll
                for (int h = 0; h < 2; h++) {
                    int rloc = wm*32 + mt*16 + g4 + h*8;
                    float v0 = c[h*2], v1 = c[h*2 + 1];
                    if (diag) {
                        if (t0 + tcol     > s0 + rloc) v0 = 0.f;
                        if (t0 + tcol + 1 > s0 + rloc) v1 = 0.f;
                    }
                    u16 h0, l0, h1, l1;
                    split_bf(v0, h0, l0);
                    split_bf(v1, h1, l1);
                    u32 off = (u32)rloc*144 + (u32)tcol*2;
                    *(u32*)(smem + SH + off) = (u32)h0 | ((u32)h1 << 16);
                    *(u32*)(smem + SL + off) = (u32)l0 | ((u32)l1 << 16);
                }
            }
        __syncthreads();

        // phase 2: Y += S·V  (M=128, N=64 d, K=64 t;  B = V^T [d][t])
        #pragma unroll
        for (int ks = 0; ks < 4; ks++) {
            int k0 = ks * 16;
            u32 ah[2][4], al[2][4];
            #pragma unroll
            for (int mt = 0; mt < 2; mt++) {
                u32 ao = (u32)((a_row + mt*16)*144 + (k0 + a_kb)*2);
                ldsm_x4(ah[mt][0], ah[mt][1], ah[mt][2], ah[mt][3], sbase + SH + ao);
                ldsm_x4(al[mt][0], al[mt][1], al[mt][2], al[mt][3], sbase + SL + ao);
            }
            #pragma unroll
            for (int nt = 0; nt < 4; nt++) {
                u32 bo = (u32)((wn*32 + nt*8 + ar)*144 + (k0 + b_kb)*2);
                u32 bh0, bh1, bl0, bl1;
                ldsm_x2(bh0, bh1, sbase + VH + bo);
                ldsm_x2(bl0, bl1, sbase + VL + bo);
                #pragma unroll
                for (int mt = 0; mt < 2; mt++) {
                    float* c = accY + (mt*4 + nt)*4;
                    mma_bf16(c, ah[mt], bh0, bh1);
                    mma_bf16(c, ah[mt], bl0, bl1);
                    mma_bf16(c, al[mt], bh0, bh1);
                }
            }
        }
    }

    // stage Y (fp32) into smem [128][68], then group-norm
    __syncthreads();
    float* stage = (float*)smem;
    #pragma unroll
    for (int mt = 0; mt < 2; mt++)
        #pragma unroll
        for (int nt = 0; nt < 4; nt++) {
            const float* c = accY + (mt*4 + nt)*4;
            int col = wn*32 + nt*8 + t4*2;
            #pragma unroll
            for (int h = 0; h < 2; h++) {
                int rloc = wm*32 + mt*16 + g4 + h*8;
                *(float2*)&stage[rloc*68 + col] = make_float2(c[h*2], c[h*2 + 1]);
            }
        }
    __syncthreads();

    float w0 = gnw[g*64 + lane], w1 = gnw[g*64 + lane + 32];
    float b0 = gnb[g*64 + lane], b1 = gnb[g*64 + lane + 32];
    for (int rr = 0; rr < 16; rr++) {
        int row = wid*16 + rr;
        float v0 = stage[row*68 + lane], v1 = stage[row*68 + lane + 32];
        float sum = v0 + v1;
        #pragma unroll
        for (int off = 16; off; off >>= 1) sum += __shfl_xor_sync(0xffffffffu, sum, off);
        float mean = sum * 0.015625f;
        float d0 = v0 - mean, d1 = v1 - mean;
        float sq = d0*d0 + d1*d1;
        #pragma unroll
        for (int off = 16; off; off >>= 1) sq += __shfl_xor_sync(0xffffffffu, sq, off);
        float rstd = rsqrtf(sq * 0.015625f + EPSV);
        float* dst = g_Yc + ((size_t)(bn*SEQ + s0 + row))*HDIM + g*64;
        dst[lane]      = d0 * rstd * w0 + b0;
        dst[lane + 32] = d1 * rstd * w1 + b1;
    }
}

// ---------------- launch -------------------------------------------------------------
extern "C" void kernel_launch(void* const* d_in, const int* in_sizes, int n_in,
                              void* d_out, int out_size)
{
    (void)in_sizes; (void)n_in; (void)out_size;
    const float* X   = (const float*)d_in[0];
    const float* Wq  = (const float*)d_in[1];
    const float* Wk  = (const float*)d_in[2];
    const float* Wv  = (const float*)d_in[3];
    const float* Wg  = (const float*)d_in[4];
    const float* Wo  = (const float*)d_in[5];
    const float* gnw = (const float*)d_in[6];
    const float* gnb = (const float*)d_in[7];
    float* out = (float*)d_out;

    const int RET_SMEM = 92160 + 18432;                        // 110592
    const int SMEM_128 = 2 * (2*128*PITCH*2 + 2*128*PITCH*2);  // 81920
    const int SMEM_64  = 2 * (2*128*PITCH*2 + 2*64*PITCH*2);   // 61440
    cudaFuncSetAttribute(ret_mma_kernel, cudaFuncAttributeMaxDynamicSharedMemorySize, RET_SMEM);
    cudaFuncSetAttribute(qkv_mma_kernel, cudaFuncAttributeMaxDynamicSharedMemorySize, SMEM_64);
    cudaFuncSetAttribute(gate_mma_kernel, cudaFuncAttributeMaxDynamicSharedMemorySize, SMEM_128);
    cudaFuncSetAttribute(out_mma_kernel, cudaFuncAttributeMaxDynamicSharedMemorySize, SMEM_128);

    tables_kernel<<<128, 256>>>();
    convX_kernel<<<ROWS*HDIM/4/256, 256>>>(X);
    convW_kernel<<<HDIM*HDIM/256, 256>>>(Wg, 0);
    convW_kernel<<<HDIM*HDIM/256, 256>>>(Wo, 1);
    convWqkv_kernel<<<3*8*HEAD*HDIM/256, 256>>>(Wq, Wk, Wv);
    qkv_mma_kernel<<<dim3(64, 24), 256, SMEM_64>>>();
    ret_mma_kernel<<<dim3(8, 64), 256, RET_SMEM>>>(gnw, gnb);
    gate_mma_kernel<<<dim3(64, 4), 256, SMEM_128>>>();
    out_mma_kernel<<<dim3(64, 4), 256, SMEM_128>>>(out);
}

// round 6
// speedup vs baseline: 2.1398x; 1.1402x over previous
#include <cuda_runtime.h>
#include <cuda_bf16.h>
#include <math.h>
#include <stdint.h>

#define SEQ   1024
#define HEAD  64
#define HDIM  512
#define BN    8
#define ROWS  (BN*SEQ)
#define EPSV  1e-5f

typedef unsigned long long u64;
typedef unsigned int u32;
typedef unsigned short u16;

// ---------------- scratch (device globals; allocation-free rule) ----------------
__device__ __align__(256) float g_sin[SEQ*32];
__device__ __align__(256) float g_cos[SEQ*32];
__device__ __align__(256) float g_scl[SEQ*32];
__device__ __align__(256) float g_Yc[ROWS*HDIM];
// bf16 hi/lo split operands
__device__ __align__(256) u16 g_Xh[ROWS*HDIM];
__device__ __align__(256) u16 g_Xl[ROWS*HDIM];
__device__ __align__(256) u16 g_Zh[ROWS*HDIM];
__device__ __align__(256) u16 g_Zl[ROWS*HDIM];
__device__ __align__(256) u16 g_WgTh[HDIM*HDIM];
__device__ __align__(256) u16 g_WgTl[HDIM*HDIM];
__device__ __align__(256) u16 g_WoTh[HDIM*HDIM];
__device__ __align__(256) u16 g_WoTl[HDIM*HDIM];
__device__ __align__(256) u16 g_WqkvTh[3*8*HEAD*HDIM];
__device__ __align__(256) u16 g_WqkvTl[3*8*HEAD*HDIM];
// retention operands, pre-scaled (decay+rotary+xpos) bf16 hi/lo
__device__ __align__(256) u16 g_Qh[8*BN*SEQ*HEAD];
__device__ __align__(256) u16 g_Ql[8*BN*SEQ*HEAD];
__device__ __align__(256) u16 g_Kh[8*BN*SEQ*HEAD];
__device__ __align__(256) u16 g_Kl[8*BN*SEQ*HEAD];
__device__ __align__(256) u16 g_Vth[8*BN*HEAD*SEQ];   // V transposed [gbn][d][t]
__device__ __align__(256) u16 g_Vtl[8*BN*HEAD*SEQ];

// ---------------- helpers ----------------------------------------------------------
__device__ __forceinline__ u32 smem_u32(const void* p) {
    u32 a;
    asm("{ .reg .u64 t; cvta.to.shared.u64 t, %1; cvt.u32.u64 %0, t; }" : "=r"(a) : "l"(p));
    return a;
}
__device__ __forceinline__ void ldsm_x4(u32& r0, u32& r1, u32& r2, u32& r3, u32 addr) {
    asm volatile("ldmatrix.sync.aligned.m8n8.x4.shared.b16 {%0,%1,%2,%3}, [%4];"
        : "=r"(r0), "=r"(r1), "=r"(r2), "=r"(r3) : "r"(addr));
}
__device__ __forceinline__ void ldsm_x2(u32& r0, u32& r1, u32 addr) {
    asm volatile("ldmatrix.sync.aligned.m8n8.x2.shared.b16 {%0,%1}, [%2];"
        : "=r"(r0), "=r"(r1) : "r"(addr));
}
__device__ __forceinline__ void mma_bf16(float* c, const u32* a, u32 b0, u32 b1) {
    asm volatile("mma.sync.aligned.m16n8k16.row.col.f32.bf16.bf16.f32 "
        "{%0,%1,%2,%3}, {%4,%5,%6,%7}, {%8,%9}, {%0,%1,%2,%3};"
        : "+f"(c[0]), "+f"(c[1]), "+f"(c[2]), "+f"(c[3])
        : "r"(a[0]), "r"(a[1]), "r"(a[2]), "r"(a[3]), "r"(b0), "r"(b1));
}
__device__ __forceinline__ void split_bf(float x, u16& h, u16& l) {
    __nv_bfloat16 hb = __float2bfloat16(x);
    __nv_bfloat16 lb = __float2bfloat16(x - __bfloat162float(hb));
    h = __bfloat16_as_ushort(hb);
    l = __bfloat16_as_ushort(lb);
}
// pack (c0, c1) -> bf16x2 hi-part hp (c0 low half) and residual lo-part lp
__device__ __forceinline__ void pack_hilo(float c0, float c1, u32& hp, u32& lp) {
    u32 h;
    asm("cvt.rn.bf16x2.f32 %0, %1, %2;" : "=r"(h) : "f"(c1), "f"(c0));
    float f0 = __uint_as_float(h << 16);
    float f1 = __uint_as_float(h & 0xffff0000u);
    asm("cvt.rn.bf16x2.f32 %0, %1, %2;" : "=r"(lp) : "f"(c1 - f1), "f"(c0 - f0));
    hp = h;
}
__device__ __forceinline__ void cp16(u32 saddr, const void* g) {
    asm volatile("cp.async.cg.shared.global [%0], [%1], 16;" :: "r"(saddr), "l"(g));
}
__device__ __forceinline__ void cp_commit() {
    asm volatile("cp.async.commit_group;" ::: "memory");
}

// ---------------- xpos tables in fp64 ---------------------------------------------
__global__ void tables_kernel() {
    int idx = blockIdx.x * blockDim.x + threadIdx.x;
    if (idx >= SEQ * 32) return;
    int s = idx >> 5, j = idx & 31;
    double inv_freq = pow(10000.0, -(double)j / 32.0);
    double ang = (double)s * inv_freq;
    g_sin[idx] = (float)sin(ang);
    g_cos[idx] = (float)cos(ang);
    double sv = (2.0 * j + 25.6) / 89.6;
    g_scl[idx] = (float)pow(sv, (double)s / 512.0);
}

// ---------------- converters -------------------------------------------------------
__global__ __launch_bounds__(256) void convX_kernel(const float* __restrict__ X) {
    int i = blockIdx.x * 256 + threadIdx.x;
    float4 v = ((const float4*)X)[i];
    ushort4 h, l;
    split_bf(v.x, h.x, l.x); split_bf(v.y, h.y, l.y);
    split_bf(v.z, h.z, l.z); split_bf(v.w, h.w, l.w);
    ((ushort4*)g_Xh)[i] = h;
    ((ushort4*)g_Xl)[i] = l;
}
__global__ __launch_bounds__(256) void convW_kernel(const float* __restrict__ W, int which) {
    int i = blockIdx.x * 256 + threadIdx.x;
    int n = i >> 9, k = i & 511;
    float x = W[(size_t)k * HDIM + n];
    u16 h, l; split_bf(x, h, l);
    u16* Th = which ? g_WoTh : g_WgTh;
    u16* Tl = which ? g_WoTl : g_WgTl;
    Th[i] = h; Tl[i] = l;
}
__global__ __launch_bounds__(256) void convWqkv_kernel(
    const float* __restrict__ Wq, const float* __restrict__ Wk, const float* __restrict__ Wv) {
    int i = blockIdx.x * 256 + threadIdx.x;
    int k = i & 511, n = (i >> 9) & 63, g = (i >> 15) & 7, mat = i >> 18;
    const float* W = (mat == 0 ? Wq : (mat == 1 ? Wk : Wv));
    float x = W[(size_t)g * HDIM * HEAD + (size_t)k * HEAD + n];
    u16 h, l; split_bf(x, h, l);
    g_WqkvTh[i] = h; g_WqkvTl[i] = l;
}

// ---------------- mma.sync bf16x3 mainloop (GEMM stages) ---------------------------
#define PITCH 40

template<int BROWS>
__device__ __forceinline__ void mma_mainloop(
    const u16* __restrict__ Ah, const u16* __restrict__ Al,
    const u16* __restrict__ Bh, const u16* __restrict__ Bl,
    char* smem, float* C)
{
    constexpr int NTI   = BROWS / 16;
    constexpr int ABYT  = 128 * PITCH * 2;
    constexpr int BBYT  = BROWS * PITCH * 2;
    constexpr int STAGE = 2 * ABYT + 2 * BBYT;
    constexpr int AGRAN = 128 * 4;
    constexpr int BGRAN = BROWS * 4;
    constexpr int NBUF  = (2 * AGRAN + 2 * BGRAN) / 256;

    int tid = threadIdx.x, lane = tid & 31, wid = tid >> 5;
    int wm = wid & 3, wn = wid >> 2;
    u32 sbase = smem_u32(smem);

    uint4 buf[NBUF];
    int garr[NBUF], grow[NBUF], gc16[NBUF];
    #pragma unroll
    for (int i = 0; i < NBUF; i++) {
        int g = i * 256 + tid;
        int arr, rem;
        if (g < AGRAN)                { arr = 0; rem = g; }
        else if (g < 2*AGRAN)         { arr = 1; rem = g - AGRAN; }
        else if (g < 2*AGRAN + BGRAN) { arr = 2; rem = g - 2*AGRAN; }
        else                          { arr = 3; rem = g - 2*AGRAN - BGRAN; }
        garr[i] = arr; grow[i] = rem >> 2; gc16[i] = rem & 3;
    }
    const u16* srcs[4] = {Ah, Al, Bh, Bl};
    const int offs[4] = {0, ABYT, 2*ABYT, 2*ABYT + BBYT};

    auto load_regs = [&](int ch) {
        int kk = ch * 32;
        #pragma unroll
        for (int i = 0; i < NBUF; i++)
            buf[i] = *(const uint4*)(srcs[garr[i]] + (size_t)grow[i] * HDIM + kk + gc16[i] * 8);
    };
    auto store_smem = [&](int st) {
        #pragma unroll
        for (int i = 0; i < NBUF; i++)
            *(uint4*)(smem + st*STAGE + offs[garr[i]] + grow[i]*(PITCH*2) + gc16[i]*16) = buf[i];
    };

    int aq = lane >> 3, ar = lane & 7;
    int a_row = wm*32 + ar + (aq & 1)*8;
    int a_kb  = (aq >> 1) * 8;
    int b_row = wn*(BROWS/2) + ar;
    int b_kb  = (lane >> 3 & 1) * 8;

    auto compute = [&](int st) {
        u32 sA_h = sbase + st*STAGE;
        u32 sA_l = sA_h + ABYT;
        u32 sB_h = sbase + st*STAGE + 2*ABYT;
        u32 sB_l = sB_h + BBYT;
        #pragma unroll
        for (int ks = 0; ks < 2; ks++) {
            int k0 = ks * 16;
            u32 ah[2][4], al[2][4];
            #pragma unroll
            for (int mt = 0; mt < 2; mt++) {
                u32 ao = (u32)((a_row + mt*16) * (PITCH*2) + (k0 + a_kb) * 2);
                ldsm_x4(ah[mt][0], ah[mt][1], ah[mt][2], ah[mt][3], sA_h + ao);
                ldsm_x4(al[mt][0], al[mt][1], al[mt][2], al[mt][3], sA_l + ao);
            }
            #pragma unroll
            for (int nt = 0; nt < NTI; nt++) {
                u32 bo = (u32)((b_row + nt*8) * (PITCH*2) + (k0 + b_kb) * 2);
                u32 bh0, bh1, bl0, bl1;
                ldsm_x2(bh0, bh1, sB_h + bo);
                ldsm_x2(bl0, bl1, sB_l + bo);
                #pragma unroll
                for (int mt = 0; mt < 2; mt++) {
                    float* c = C + (mt*NTI + nt)*4;
                    mma_bf16(c, ah[mt], bh0, bh1);
                    mma_bf16(c, ah[mt], bl0, bl1);
                    mma_bf16(c, al[mt], bh0, bh1);
                }
            }
        }
    };

    load_regs(0);
    store_smem(0);
    __syncthreads();
    #pragma unroll 1
    for (int ch = 0; ch < 16; ch++) {
        if (ch < 15) load_regs(ch + 1);
        compute(ch & 1);
        if (ch < 15) store_smem((ch + 1) & 1);
        __syncthreads();
    }
}

// ---------------- QKV GEMM + rotary/decay epilogue -> bf16 hi/lo --------------------
// grid: (64 row-tiles, 24 = mat*8+g), block 256
__global__ __launch_bounds__(256) void qkv_mma_kernel() {
    extern __shared__ __align__(128) char smem[];
    int rowTile = blockIdx.x * 128;
    int mat = blockIdx.y >> 3, g = blockIdx.y & 7;

    float C[2*4*4] = {};
    mma_mainloop<64>(g_Xh + (size_t)rowTile*HDIM, g_Xl + (size_t)rowTile*HDIM,
                     g_WqkvTh + (size_t)(mat*8 + g)*HEAD*HDIM,
                     g_WqkvTl + (size_t)(mat*8 + g)*HEAD*HDIM, smem, C);

    int tid = threadIdx.x, lane = tid & 31, wid = tid >> 5;
    int wm = wid & 3, wn = wid >> 2, g4 = lane >> 2, t4 = lane & 3;
    int bn = rowTile >> 10, sb = rowTile & 1023;
    size_t gbn = (size_t)(g*8 + bn);

    if (mat == 2) {
        // stage V transposed [d][s] hi/lo in smem, then coalesced copy out
        u16* sVh = (u16*)smem;             // [64][136]
        u16* sVl = (u16*)smem + 64*136;
        #pragma unroll
        for (int mt = 0; mt < 2; mt++)
            #pragma unroll
            for (int nt = 0; nt < 4; nt++) {
                const float* c = C + (mt*4 + nt)*4;
                int col = wn*32 + nt*8 + t4*2;
                #pragma unroll
                for (int h = 0; h < 2; h++) {
                    int rloc = wm*32 + mt*16 + g4 + h*8;
                    u32 hp, lp;
                    pack_hilo(c[h*2], c[h*2+1], hp, lp);
                    sVh[col*136 + rloc]       = (u16)(hp & 0xffffu);
                    sVh[(col+1)*136 + rloc]   = (u16)(hp >> 16);
                    sVl[col*136 + rloc]       = (u16)(lp & 0xffffu);
                    sVl[(col+1)*136 + rloc]   = (u16)(lp >> 16);
                }
            }
        __syncthreads();
        #pragma unroll
        for (int p = 0; p < 4; p++) {
            int lin = p*256 + tid;
            int d = lin >> 4, c16 = lin & 15;
            *(uint4*)&g_Vth[(gbn*HEAD + d)*SEQ + sb + c16*8] = *(const uint4*)&sVh[d*136 + c16*8];
            *(uint4*)&g_Vtl[(gbn*HEAD + d)*SEQ + sb + c16*8] = *(const uint4*)&sVl[d*136 + c16*8];
        }
    } else {
        double lgd = log(1.0/32.0) + (double)g * ((log(1.0/512.0) - log(1.0/32.0)) / 7.0);
        float log2g = (float)log2(1.0 - exp(lgd));
        float sgn = (mat == 0) ? 1.f : -1.f;
        float fdecay[2][2];
        #pragma unroll
        for (int mt = 0; mt < 2; mt++)
            #pragma unroll
            for (int h = 0; h < 2; h++)
                fdecay[mt][h] = exp2f(sgn * (float)(sb + wm*32 + mt*16 + g4 + h*8) * log2g);

        u16* Dh = (mat == 0) ? g_Qh : g_Kh;
        u16* Dl = (mat == 0) ? g_Ql : g_Kl;
        #pragma unroll
        for (int mt = 0; mt < 2; mt++)
            #pragma unroll
            for (int nt = 0; nt < 4; nt++) {
                const float* c = C + (mt*4 + nt)*4;
                int col = wn*32 + nt*8 + t4*2;
                int j2 = col >> 1;
                #pragma unroll
                for (int h = 0; h < 2; h++) {
                    int s = sb + wm*32 + mt*16 + g4 + h*8;
                    float sn = g_sin[s*32 + j2], cs = g_cos[s*32 + j2], sc = g_scl[s*32 + j2];
                    float e = c[h*2], o = c[h*2 + 1];
                    float re = e*cs - o*sn;
                    float ro = o*cs + e*sn;
                    float m = ((mat == 0) ? sc : 1.0f/sc) * fdecay[mt][h];
                    u32 hp, lp;
                    pack_hilo(re*m, ro*m, hp, lp);
                    size_t off = (gbn*SEQ + s)*HEAD + col;
                    *(u32*)&Dh[off] = hp;
                    *(u32*)&Dl[off] = lp;
                }
            }
    }
}

// ---------------- gate GEMM: Z = silu(X@Wg)*Yc -> bf16 hi/lo ------------------------
__global__ __launch_bounds__(256) void gate_mma_kernel() {
    extern __shared__ __align__(128) char smem[];
    int rowTile = blockIdx.x * 128, ct = blockIdx.y * 128;

    float C[2*8*4] = {};
    mma_mainloop<128>(g_Xh + (size_t)rowTile*HDIM, g_Xl + (size_t)rowTile*HDIM,
                      g_WgTh + (size_t)ct*HDIM, g_WgTl + (size_t)ct*HDIM, smem, C);

    int tid = threadIdx.x, lane = tid & 31, wid = tid >> 5;
    int wm = wid & 3, wn = wid >> 2, g4 = lane >> 2, t4 = lane & 3;

    #pragma unroll
    for (int mt = 0; mt < 2; mt++)
        #pragma unroll
        for (int nt = 0; nt < 8; nt++) {
            const float* c = C + (mt*8 + nt)*4;
            int col = ct + wn*64 + nt*8 + t4*2;
            #pragma unroll
            for (int h = 0; h < 2; h++) {
                int row = rowTile + wm*32 + mt*16 + g4 + h*8;
                size_t off = (size_t)row*HDIM + col;
                float2 y = *(const float2*)&g_Yc[off];
                float v0 = c[h*2], v1 = c[h*2 + 1];
                float z0 = v0 / (1.0f + expf(-v0)) * y.x;
                float z1 = v1 / (1.0f + expf(-v1)) * y.y;
                u32 hp, lp;
                pack_hilo(z0, z1, hp, lp);
                *(u32*)&g_Zh[off] = hp;
                *(u32*)&g_Zl[off] = lp;
            }
        }
}

// ---------------- output GEMM: out = Z @ Wo ------------------------------------------
__global__ __launch_bounds__(256) void out_mma_kernel(float* __restrict__ out) {
    extern __shared__ __align__(128) char smem[];
    int rowTile = blockIdx.x * 128, ct = blockIdx.y * 128;

    float C[2*8*4] = {};
    mma_mainloop<128>(g_Zh + (size_t)rowTile*HDIM, g_Zl + (size_t)rowTile*HDIM,
                      g_WoTh + (size_t)ct*HDIM, g_WoTl + (size_t)ct*HDIM, smem, C);

    int tid = threadIdx.x, lane = tid & 31, wid = tid >> 5;
    int wm = wid & 3, wn = wid >> 2, g4 = lane >> 2, t4 = lane & 3;

    #pragma unroll
    for (int mt = 0; mt < 2; mt++)
        #pragma unroll
        for (int nt = 0; nt < 8; nt++) {
            const float* c = C + (mt*8 + nt)*4;
            int col = ct + wn*64 + nt*8 + t4*2;
            #pragma unroll
            for (int h = 0; h < 2; h++) {
                int row = rowTile + wm*32 + mt*16 + g4 + h*8;
                *(float2*)&out[(size_t)row*HDIM + col] = make_float2(c[h*2], c[h*2 + 1]);
            }
        }
}

// ---------------- retention via tensor cores (register S, cp.async pipeline) --------
// grid: (8, 64 = gbn), block 256 (8 warps, 4x2).
// smem: Qh [128][72] @0 (18432), Ql @18432; K/V stages x2 @36864:
//   per stage (36864B): Kh [64][72] @0, Kl @9216, Vth [64][72] @18432, Vtl @27648.
__global__ __launch_bounds__(256) void ret_mma_kernel(
    const float* __restrict__ gnw, const float* __restrict__ gnb)
{
    extern __shared__ __align__(128) char smem[];
    const int QH = 0, QL = 18432, STG = 36864, SSZ = 36864;
    const int KHo = 0, KLo = 9216, VHo = 18432, VLo = 27648;
    u32 sbase = smem_u32(smem);

    int tid = threadIdx.x, lane = tid & 31, wid = tid >> 5;
    int wm = wid & 3, wn = wid >> 2;
    int g4 = lane >> 2, t4 = lane & 3;
    int bx = 7 - (int)blockIdx.x;            // heavy tiles first
    int gbn = blockIdx.y, g = gbn >> 3, bn = gbn & 7;
    int s0 = bx * 128;

    const u16* Qh = g_Qh + ((size_t)gbn*SEQ + s0)*HEAD;
    const u16* Ql = g_Ql + ((size_t)gbn*SEQ + s0)*HEAD;
    const u16* Kh = g_Kh + (size_t)gbn*SEQ*HEAD;
    const u16* Kl = g_Kl + (size_t)gbn*SEQ*HEAD;
    const u16* Vh = g_Vth + (size_t)gbn*HEAD*SEQ;
    const u16* Vl = g_Vtl + (size_t)gbn*HEAD*SEQ;

    // Q tile: 128 rows x 64 bf16 x2 arrays via cp.async
    #pragma unroll
    for (int p = 0; p < 4; p++) {
        int lin = p*256 + tid;
        int r = lin >> 3, c16 = lin & 7;
        cp16(sbase + QH + r*144 + c16*16, Qh + (size_t)r*HEAD + c16*8);
        cp16(sbase + QL + r*144 + c16*16, Ql + (size_t)r*HEAD + c16*8);
    }

    auto load_tile = [&](int jt) {
        int t0 = jt * 64;
        u32 sb2 = sbase + STG + (jt & 1)*SSZ;
        #pragma unroll
        for (int p = 0; p < 2; p++) {
            int lin = p*256 + tid;
            int r = lin >> 3, c16 = lin & 7;
            cp16(sb2 + KHo + r*144 + c16*16, Kh + (size_t)(t0 + r)*HEAD + c16*8);
            cp16(sb2 + KLo + r*144 + c16*16, Kl + (size_t)(t0 + r)*HEAD + c16*8);
            cp16(sb2 + VHo + r*144 + c16*16, Vh + (size_t)r*SEQ + t0 + c16*8);
            cp16(sb2 + VLo + r*144 + c16*16, Vl + (size_t)r*SEQ + t0 + c16*8);
        }
        cp_commit();
    };
    load_tile(0);

    int aq = lane >> 3, ar = lane & 7;
    int a_row = wm*32 + ar + (aq & 1)*8;
    int a_kb  = (aq >> 1) * 8;
    int b_kb  = (aq & 1) * 8;

    float accY[2*8*4] = {};
    int jtmax = 2*bx + 1;
    for (int jt = 0; jt <= jtmax; jt++) {
        int t0 = jt * 64;
        asm volatile("cp.async.wait_group 0;" ::: "memory");
        __syncthreads();
        if (jt < jtmax) load_tile(jt + 1);

        u32 stg = sbase + STG + (jt & 1)*SSZ;
        u32 sK_h = stg + KHo, sK_l = stg + KLo;
        u32 sV_h = stg + VHo, sV_l = stg + VLo;
        bool diag = (jt >= 2*bx);

        #pragma unroll
        for (int kt = 0; kt < 2; kt++) {
            // phase 1: S chunk = Q'·K'^T over this warp's k16 (t) slice pair
            float accS[2][2][4] = {};
            #pragma unroll
            for (int ks = 0; ks < 4; ks++) {
                int k0 = ks * 16;
                u32 ah[2][4], al[2][4];
                #pragma unroll
                for (int mt = 0; mt < 2; mt++) {
                    u32 ao = (u32)((a_row + mt*16)*144 + (k0 + a_kb)*2);
                    ldsm_x4(ah[mt][0], ah[mt][1], ah[mt][2], ah[mt][3], sbase + QH + ao);
                    ldsm_x4(al[mt][0], al[mt][1], al[mt][2], al[mt][3], sbase + QL + ao);
                }
                #pragma unroll
                for (int ntp = 0; ntp < 2; ntp++) {
                    u32 bo = (u32)((wn*32 + kt*16 + ntp*8 + ar)*144 + (k0 + b_kb)*2);
                    u32 bh0, bh1, bl0, bl1;
                    ldsm_x2(bh0, bh1, sK_h + bo);
                    ldsm_x2(bl0, bl1, sK_l + bo);
                    #pragma unroll
                    for (int mt = 0; mt < 2; mt++) {
                        float* c = accS[mt][ntp];
                        mma_bf16(c, ah[mt], bh0, bh1);
                        mma_bf16(c, ah[mt], bl0, bl1);
                        mma_bf16(c, al[mt], bh0, bh1);
                    }
                }
            }
            // mask + pack S into phase-2 A fragments (register hand-off)
            u32 sa_h[2][4], sa_l[2][4];
            #pragma unroll
            for (int mt = 0; mt < 2; mt++) {
                #pragma unroll
                for (int ntp = 0; ntp < 2; ntp++) {
                    float* c = accS[mt][ntp];
                    if (diag) {
                        int tb = t0 + wn*32 + kt*16 + ntp*8 + t4*2;
                        int sg0 = s0 + wm*32 + mt*16 + g4;
                        if (tb     > sg0)     c[0] = 0.f;
                        if (tb + 1 > sg0)     c[1] = 0.f;
                        if (tb     > sg0 + 8) c[2] = 0.f;
                        if (tb + 1 > sg0 + 8) c[3] = 0.f;
                    }
                    pack_hilo(c[0], c[1], sa_h[mt][ntp*2],     sa_l[mt][ntp*2]);
                    pack_hilo(c[2], c[3], sa_h[mt][ntp*2 + 1], sa_l[mt][ntp*2 + 1]);
                }
            }
            // phase 2: Y += S·V over this k16 slice, all 64 d columns
            #pragma unroll
            for (int nt2 = 0; nt2 < 8; nt2++) {
                u32 bo = (u32)((nt2*8 + ar)*144 + (wn*32 + kt*16 + b_kb)*2);
                u32 bh0, bh1, bl0, bl1;
                ldsm_x2(bh0, bh1, sV_h + bo);
                ldsm_x2(bl0, bl1, sV_l + bo);
                #pragma unroll
                for (int mt = 0; mt < 2; mt++) {
                    float* c = accY + (mt*8 + nt2)*4;
                    mma_bf16(c, sa_h[mt], bh0, bh1);
                    mma_bf16(c, sa_h[mt], bl0, bl1);
                    mma_bf16(c, sa_l[mt], bh0, bh1);
                }
            }
        }
    }

    // cross-warp (wn) Y reduction into smem stage, then group-norm
    __syncthreads();
    float* stage = (float*)smem;   // [128][68]
    if (wn == 0) {
        #pragma unroll
        for (int mt = 0; mt < 2; mt++)
            #pragma unroll
            for (int nt2 = 0; nt2 < 8; nt2++) {
                const float* c = accY + (mt*8 + nt2)*4;
                int col = nt2*8 + t4*2;
                #pragma unroll
                for (int h = 0; h < 2; h++) {
                    int rloc = wm*32 + mt*16 + g4 + h*8;
                    *(float2*)&stage[rloc*68 + col] = make_float2(c[h*2], c[h*2 + 1]);
                }
            }
    }
    __syncthreads();
    if (wn == 1) {
        #pragma unroll
        for (int mt = 0; mt < 2; mt++)
            #pragma unroll
            for (int nt2 = 0; nt2 < 8; nt2++) {
                const float* c = accY + (mt*8 + nt2)*4;
                int col = nt2*8 + t4*2;
                #pragma unroll
                for (int h = 0; h < 2; h++) {
                    int rloc = wm*32 + mt*16 + g4 + h*8;
                    float2 v = *(const float2*)&stage[rloc*68 + col];
                    v.x += c[h*2]; v.y += c[h*2 + 1];
                    *(float2*)&stage[rloc*68 + col] = v;
                }
            }
    }
    __syncthreads();

    float w0 = gnw[g*64 + lane], w1 = gnw[g*64 + lane + 32];
    float b0 = gnb[g*64 + lane], b1 = gnb[g*64 + lane + 32];
    for (int rr = 0; rr < 16; rr++) {
        int row = wid*16 + rr;
        float v0 = stage[row*68 + lane], v1 = stage[row*68 + lane + 32];
        float sum = v0 + v1;
        #pragma unroll
        for (int off = 16; off; off >>= 1) sum += __shfl_xor_sync(0xffffffffu, sum, off);
        float mean = sum * 0.015625f;
        float d0 = v0 - mean, d1 = v1 - mean;
        float sq = d0*d0 + d1*d1;
        #pragma unroll
        for (int off = 16; off; off >>= 1) sq += __shfl_xor_sync(0xffffffffu, sq, off);
        float rstd = rsqrtf(sq * 0.015625f + EPSV);
        float* dst = g_Yc + ((size_t)(bn*SEQ + s0 + row))*HDIM + g*64;
        dst[lane]      = d0 * rstd * w0 + b0;
        dst[lane + 32] = d1 * rstd * w1 + b1;
    }
}

// ---------------- launch -------------------------------------------------------------
extern "C" void kernel_launch(void* const* d_in, const int* in_sizes, int n_in,
                              void* d_out, int out_size)
{
    (void)in_sizes; (void)n_in; (void)out_size;
    const float* X   = (const float*)d_in[0];
    const float* Wq  = (const float*)d_in[1];
    const float* Wk  = (const float*)d_in[2];
    const float* Wv  = (const float*)d_in[3];
    const float* Wg  = (const float*)d_in[4];
    const float* Wo  = (const float*)d_in[5];
    const float* gnw = (const float*)d_in[6];
    const float* gnb = (const float*)d_in[7];
    float* out = (float*)d_out;

    const int RET_SMEM = 36864 + 2*36864;                      // 110592
    const int SMEM_128 = 2 * (2*128*PITCH*2 + 2*128*PITCH*2);  // 81920
    const int SMEM_64  = 2 * (2*128*PITCH*2 + 2*64*PITCH*2);   // 61440
    cudaFuncSetAttribute(ret_mma_kernel, cudaFuncAttributeMaxDynamicSharedMemorySize, RET_SMEM);
    cudaFuncSetAttribute(qkv_mma_kernel, cudaFuncAttributeMaxDynamicSharedMemorySize, SMEM_64);
    cudaFuncSetAttribute(gate_mma_kernel, cudaFuncAttributeMaxDynamicSharedMemorySize, SMEM_128);
    cudaFuncSetAttribute(out_mma_kernel, cudaFuncAttributeMaxDynamicSharedMemorySize, SMEM_128);

    tables_kernel<<<128, 256>>>();
    convX_kernel<<<ROWS*HDIM/4/256, 256>>>(X);
    convW_kernel<<<HDIM*HDIM/256, 256>>>(Wg, 0);
    convW_kernel<<<HDIM*HDIM/256, 256>>>(Wo, 1);
    convWqkv_kernel<<<3*8*HEAD*HDIM/256, 256>>>(Wq, Wk, Wv);
    qkv_mma_kernel<<<dim3(64, 24), 256, SMEM_64>>>();
    ret_mma_kernel<<<dim3(8, 64), 256, RET_SMEM>>>(gnw, gnb);
    gate_mma_kernel<<<dim3(64, 4), 256, SMEM_128>>>();
    out_mma_kernel<<<dim3(64, 4), 256, SMEM_128>>>(out);
}